// round 6
// baseline (speedup 1.0000x reference)
#include <cuda_runtime.h>
#include <math.h>
#include <cstdint>

#define MAX_BN 8192
#define MAX_L  256
#define MAX_NB 64
__device__ float g_xp [MAX_BN * MAX_L];   // fp32 projection (for h + fallback)
__device__ float g_xpt[MAX_BN * MAX_L];   // tf32-rounded copy (for tensor GEMM)
__device__ int   g_flags[MAX_BN];
__device__ int   g_argmin[MAX_BN];
__device__ float g_pmin [MAX_BN * MAX_NB];
__device__ float g_pmin2[MAX_BN * MAX_NB];
__device__ float g_pmax [MAX_BN * MAX_NB];
__device__ int   g_pidx [MAX_BN * MAX_NB];

// ---------- helpers ----------
__device__ __forceinline__ unsigned f2key(float f) {
    unsigned u = __float_as_uint(f);
    return (u & 0x80000000u) ? ~u : (u | 0x80000000u);
}
__device__ __forceinline__ float key2f(unsigned k) {
    unsigned u = (k & 0x80000000u) ? (k & 0x7fffffffu) : ~k;
    return __uint_as_float(u);
}
__device__ __forceinline__ float to_tf32(float f) {
    unsigned o;
    asm("cvt.rna.tf32.f32 %0, %1;" : "=r"(o) : "f"(f));
    return __uint_as_float(o);
}
__device__ __forceinline__ void mma_tf32(float* d, const unsigned* a, const unsigned* b) {
    asm volatile(
        "mma.sync.aligned.m16n8k8.row.col.f32.tf32.tf32.f32 "
        "{%0,%1,%2,%3}, {%4,%5,%6,%7}, {%8,%9}, {%0,%1,%2,%3};"
        : "+f"(d[0]), "+f"(d[1]), "+f"(d[2]), "+f"(d[3])
        : "r"(a[0]), "r"(a[1]), "r"(a[2]), "r"(a[3]),
          "r"(b[0]), "r"(b[1]));
}

// ---------- Kernel 1: x_proj = x @ W^T (writes fp32 + tf32 copies) ----------
#define PROJ_ROWS 8
__global__ void proj_kernel(const float* __restrict__ x,
                            const float* __restrict__ W,
                            int BN, int L) {
    __shared__ float xs[PROJ_ROWS * 256];
    __shared__ float Ws[32][257];
    int n0 = blockIdx.x * PROJ_ROWS;
    int rows = min(PROJ_ROWS, BN - n0);
    int t = threadIdx.x;
    for (int i = t; i < rows * L; i += 256) xs[i] = x[(size_t)n0 * L + i];

    float acc[PROJ_ROWS];
#pragma unroll
    for (int r = 0; r < PROJ_ROWS; r++) acc[r] = 0.f;

    for (int l0 = 0; l0 < L; l0 += 32) {
        int lw = min(32, L - l0);
        __syncthreads();
        for (int idx = t; idx < L * lw; idx += 256) {
            int o = idx / lw, l = idx - o * lw;
            Ws[l][o] = W[(size_t)o * L + l0 + l];
        }
        __syncthreads();
        if (t < L) {
            for (int l = 0; l < lw; l++) {
                float w = Ws[l][t];
#pragma unroll
                for (int r = 0; r < PROJ_ROWS; r++)
                    acc[r] += xs[r * L + l0 + l] * w;
            }
        }
    }
    if (t < L)
        for (int r = 0; r < rows; r++) {
            size_t o = (size_t)(n0 + r) * L + t;
            g_xp[o]  = acc[r];
            g_xpt[o] = to_tf32(acc[r]);
        }
}

// ---------- bounds-safe float4 load ----------
__device__ __forceinline__ float4 ldxp4(const float* __restrict__ base,
                                        int row, int k, int N, int L) {
    float4 v = make_float4(0.f, 0.f, 0.f, 0.f);
    if (row < N) {
        const float* p = base + (size_t)row * L + k;
        if (k + 3 < L) {
            if ((((unsigned long long)(uintptr_t)p) & 15ull) == 0)
                v = *(const float4*)p;
            else { v.x = p[0]; v.y = p[1]; v.z = p[2]; v.w = p[3]; }
        } else {
            if (k     < L) v.x = p[0];
            if (k + 1 < L) v.y = p[1];
            if (k + 2 < L) v.z = p[2];
        }
    }
    return v;
}

// ---------- Kernel 2: tf32 tensor-core score GEMM -> per-row strip statistics ---
// Block = 256 threads = 8 warps (2 warp-rows x 4 warp-cols); tile 128x128;
// warp tile 64x32 via m16n8k8 (4 m-tiles x 4 n-tiles).
__global__ __launch_bounds__(256, 2)
void score_stats_kernel(int N, int L, int nb) {
    int b = blockIdx.y;
    const float* base = g_xpt + (size_t)b * N * L;

    // triangular block mapping (bj >= bi)
    int t = blockIdx.x;
    int bi;
    {
        float fnb = (float)(2 * nb + 1);
        int est = (int)((fnb - sqrtf(fnb * fnb - 8.0f * (float)t)) * 0.5f);
        if (est < 0) est = 0;
        if (est >= nb) est = nb - 1;
        bi = est;
        while (bi > 0 && (bi * nb - bi * (bi - 1) / 2) > t) bi--;
        while (((bi + 1) * nb - (bi + 1) * bi / 2) <= t) bi++;
    }
    int bj = bi + (t - (bi * nb - bi * (bi - 1) / 2));
    int i0 = bi * 128, j0 = bj * 128;

    __shared__ __align__(16) float As[2][8][136];   // [k][row], stride 136 (=8 mod 32)
    __shared__ __align__(16) float Bs[2][8][136];   // [k][col]
    __shared__ float sred[128][17];
    __shared__ int   sredi[128][17];

    int tid  = threadIdx.x;
    int lane = tid & 31, wid = tid >> 5;
    int wm = wid >> 2, wn = wid & 3;      // warp grid 2 x 4
    int gid = lane >> 2, tig = lane & 3;  // mma fragment coords
    int lr = tid & 127;                    // row for smem fill
    int lh = (tid >> 7) * 4;               // k-offset 0/4 for smem fill

    float acc[4][4][4] = {};

    int nk = (L + 7) / 8;

    // prefetch chunk 0
    {
        float4 av = ldxp4(base, i0 + lr, lh, N, L);
        float4 bv = ldxp4(base, j0 + lr, lh, N, L);
        As[0][lh + 0][lr] = av.x; As[0][lh + 1][lr] = av.y;
        As[0][lh + 2][lr] = av.z; As[0][lh + 3][lr] = av.w;
        Bs[0][lh + 0][lr] = bv.x; Bs[0][lh + 1][lr] = bv.y;
        Bs[0][lh + 2][lr] = bv.z; Bs[0][lh + 3][lr] = bv.w;
    }
    __syncthreads();

    int buf = 0;
    for (int kc = 0; kc < nk; kc++) {
        float4 an, bn;
        bool has = (kc + 1 < nk);
        if (has) {
            an = ldxp4(base, i0 + lr, (kc + 1) * 8 + lh, N, L);
            bn = ldxp4(base, j0 + lr, (kc + 1) * 8 + lh, N, L);
        }

        // B fragments (8 regs)
        unsigned bfr[4][2];
#pragma unroll
        for (int nt = 0; nt < 4; nt++) {
            int col = wn * 32 + nt * 8 + gid;
            bfr[nt][0] = __float_as_uint(Bs[buf][tig][col]);
            bfr[nt][1] = __float_as_uint(Bs[buf][tig + 4][col]);
        }
        // A fragments per m-tile + 4 mmas each
#pragma unroll
        for (int mt = 0; mt < 4; mt++) {
            int row = wm * 64 + mt * 16 + gid;
            unsigned afr[4];
            afr[0] = __float_as_uint(As[buf][tig][row]);
            afr[1] = __float_as_uint(As[buf][tig][row + 8]);
            afr[2] = __float_as_uint(As[buf][tig + 4][row]);
            afr[3] = __float_as_uint(As[buf][tig + 4][row + 8]);
#pragma unroll
            for (int nt = 0; nt < 4; nt++)
                mma_tf32(acc[mt][nt], afr, bfr[nt]);
        }

        if (has) {
            int nb2 = buf ^ 1;
            As[nb2][lh + 0][lr] = an.x; As[nb2][lh + 1][lr] = an.y;
            As[nb2][lh + 2][lr] = an.z; As[nb2][lh + 3][lr] = an.w;
            Bs[nb2][lh + 0][lr] = bn.x; Bs[nb2][lh + 1][lr] = bn.y;
            Bs[nb2][lh + 2][lr] = bn.z; Bs[nb2][lh + 3][lr] = bn.w;
        }
        __syncthreads();
        buf ^= 1;
    }

    const float INF = 3.4e38f;
    // thread's element coords:
    //  row(mt,hh) = wm*64 + mt*16 + gid + 8*hh ; col(nt,r) = wn*32 + nt*8 + 2*tig + r
    //  value = acc[mt][nt][2*hh + r]

    float rm1 = INF, rm2 = INF, rmx = -INF;
    int ridx = 0x7fffffff;

    // =========== Phase A: stats over j-cols for each i-row ==========
    // pass 1: m1 + idx
#pragma unroll
    for (int mt = 0; mt < 4; mt++)
#pragma unroll
        for (int hh = 0; hh < 2; hh++) {
            int lrow = wm * 64 + mt * 16 + gid + 8 * hh;
            float m1 = INF; int idx = 0x7fffffff;
#pragma unroll
            for (int nt = 0; nt < 4; nt++)
#pragma unroll
                for (int r = 0; r < 2; r++) {
                    int col = j0 + wn * 32 + nt * 8 + 2 * tig + r;
                    float v = acc[mt][nt][2 * hh + r];
                    if (col < N && v < m1) { m1 = v; idx = col; }
                }
            sred[lrow][wn * 4 + tig] = m1;
            sredi[lrow][wn * 4 + tig] = idx;
        }
    __syncthreads();
    float rm2a = INF;
    if (tid < 128) {
        rm1 = INF; ridx = 0x7fffffff;
#pragma unroll
        for (int q = 0; q < 16; q++) {
            float v = sred[tid][q]; int ix = sredi[tid][q];
            if (v < rm1) { rm2a = rm1; rm1 = v; ridx = ix; }
            else if (v == rm1) { rm2a = v; ridx = min(ridx, ix); }
            else if (v < rm2a) rm2a = v;
        }
    }
    __syncthreads();
    // pass 2: m2 (second smallest incl. duplicates, per thread-row)
#pragma unroll
    for (int mt = 0; mt < 4; mt++)
#pragma unroll
        for (int hh = 0; hh < 2; hh++) {
            int lrow = wm * 64 + mt * 16 + gid + 8 * hh;
            float m1 = INF, m2 = INF;
#pragma unroll
            for (int nt = 0; nt < 4; nt++)
#pragma unroll
                for (int r = 0; r < 2; r++) {
                    int col = j0 + wn * 32 + nt * 8 + 2 * tig + r;
                    float v = acc[mt][nt][2 * hh + r];
                    if (col < N) {
                        if (v < m1) { m2 = m1; m1 = v; }
                        else if (v < m2) m2 = v;
                    }
                }
            sred[lrow][wn * 4 + tig] = m2;
        }
    __syncthreads();
    if (tid < 128) {
        rm2 = rm2a;
#pragma unroll
        for (int q = 0; q < 16; q++) rm2 = fminf(rm2, sred[tid][q]);
    }
    __syncthreads();
    // pass 3: max
#pragma unroll
    for (int mt = 0; mt < 4; mt++)
#pragma unroll
        for (int hh = 0; hh < 2; hh++) {
            int lrow = wm * 64 + mt * 16 + gid + 8 * hh;
            float mx = -INF;
#pragma unroll
            for (int nt = 0; nt < 4; nt++)
#pragma unroll
                for (int r = 0; r < 2; r++) {
                    int col = j0 + wn * 32 + nt * 8 + 2 * tig + r;
                    float v = acc[mt][nt][2 * hh + r];
                    if (col < N) mx = fmaxf(mx, v);
                }
            sred[lrow][wn * 4 + tig] = mx;
        }
    __syncthreads();
    if (tid < 128) {
        rmx = -INF;
#pragma unroll
        for (int q = 0; q < 16; q++) rmx = fmaxf(rmx, sred[tid][q]);
        if (i0 + tid < N) {
            size_t o = (size_t)(b * N + i0 + tid) * MAX_NB + bj;
            g_pmin[o] = rm1; g_pmin2[o] = rm2; g_pmax[o] = rmx; g_pidx[o] = ridx;
        }
    }

    // =========== Phase B (mirror): stats over i-rows for each j-col ==========
    if (bi != bj) {
        __syncthreads();
        // pass 1: m1 + idx
#pragma unroll
        for (int nt = 0; nt < 4; nt++)
#pragma unroll
            for (int r = 0; r < 2; r++) {
                int lcol = wn * 32 + nt * 8 + 2 * tig + r;
                float m1 = INF; int idx = 0x7fffffff;
#pragma unroll
                for (int mt = 0; mt < 4; mt++)
#pragma unroll
                    for (int hh = 0; hh < 2; hh++) {
                        int grow = i0 + wm * 64 + mt * 16 + gid + 8 * hh;
                        float v = acc[mt][nt][2 * hh + r];
                        if (grow < N && v < m1) { m1 = v; idx = grow; }
                    }
                sred[lcol][wm * 8 + gid] = m1;
                sredi[lcol][wm * 8 + gid] = idx;
            }
        __syncthreads();
        rm2a = INF;
        if (tid < 128) {
            rm1 = INF; ridx = 0x7fffffff;
#pragma unroll
            for (int q = 0; q < 16; q++) {
                float v = sred[tid][q]; int ix = sredi[tid][q];
                if (v < rm1) { rm2a = rm1; rm1 = v; ridx = ix; }
                else if (v == rm1) { rm2a = v; ridx = min(ridx, ix); }
                else if (v < rm2a) rm2a = v;
            }
        }
        __syncthreads();
        // pass 2: m2
#pragma unroll
        for (int nt = 0; nt < 4; nt++)
#pragma unroll
            for (int r = 0; r < 2; r++) {
                int lcol = wn * 32 + nt * 8 + 2 * tig + r;
                float m1 = INF, m2 = INF;
#pragma unroll
                for (int mt = 0; mt < 4; mt++)
#pragma unroll
                    for (int hh = 0; hh < 2; hh++) {
                        int grow = i0 + wm * 64 + mt * 16 + gid + 8 * hh;
                        float v = acc[mt][nt][2 * hh + r];
                        if (grow < N) {
                            if (v < m1) { m2 = m1; m1 = v; }
                            else if (v < m2) m2 = v;
                        }
                    }
                sred[lcol][wm * 8 + gid] = m2;
            }
        __syncthreads();
        if (tid < 128) {
            rm2 = rm2a;
#pragma unroll
            for (int q = 0; q < 16; q++) rm2 = fminf(rm2, sred[tid][q]);
        }
        __syncthreads();
        // pass 3: max
#pragma unroll
        for (int nt = 0; nt < 4; nt++)
#pragma unroll
            for (int r = 0; r < 2; r++) {
                int lcol = wn * 32 + nt * 8 + 2 * tig + r;
                float mx = -INF;
#pragma unroll
                for (int mt = 0; mt < 4; mt++)
#pragma unroll
                    for (int hh = 0; hh < 2; hh++) {
                        int grow = i0 + wm * 64 + mt * 16 + gid + 8 * hh;
                        float v = acc[mt][nt][2 * hh + r];
                        if (grow < N) mx = fmaxf(mx, v);
                    }
                sred[lcol][wm * 8 + gid] = mx;
            }
        __syncthreads();
        if (tid < 128) {
            rmx = -INF;
#pragma unroll
            for (int q = 0; q < 16; q++) rmx = fmaxf(rmx, sred[tid][q]);
            if (j0 + tid < N) {
                size_t o = (size_t)(b * N + j0 + tid) * MAX_NB + bi;
                g_pmin[o] = rm1; g_pmin2[o] = rm2; g_pmax[o] = rmx; g_pidx[o] = ridx;
            }
        }
    }
}

// ---------- Kernel 3: merge strip stats -> argmin + guard flag per row ----------
__global__ void merge_kernel(int BN, int N, int nb, int K) {
    int n = blockIdx.x * 256 + threadIdx.x;
    if (n >= BN) return;
    const float INF = 3.4e38f;
    float m1 = INF, m2 = INF, mx = -INF;
    int idx = 0x7fffffff;
    size_t base = (size_t)n * MAX_NB;
    for (int s = 0; s < nb; s++) {
        float pm1 = g_pmin[base + s];
        float pm2 = g_pmin2[base + s];
        float px  = g_pmax[base + s];
        int   pi  = g_pidx[base + s];
        mx = fmaxf(mx, px);
        if (pm1 < m1) {
            m2 = fminf(m1, pm2);
            m1 = pm1; idx = pi;
        } else if (pm1 == m1) {
            m2 = m1;                 // duplicate min across strips -> not unique
            idx = min(idx, pi);
        } else {
            m2 = fminf(m2, pm1);
        }
    }
    // guards: one-hot exactness + tf32-noise margin on the argmin gap
    float thr = fmaxf(1e-5f, 4e-3f * fmaxf(fabsf(m1), fabsf(mx)));
    bool ok = (m1 < 0.f)
           && (-m1 > (mx + 256.f) * 1e-19f)
           && (m2 - m1 > thr)
           && (N > K + 1);
    g_flags[n]  = ok ? 0 : 1;
    g_argmin[n] = idx;
}

// ---------- Kernel 4: one-hot attention fill + h gather (write-only) ------------
__global__ void fill_kernel(float* __restrict__ h_out,
                            float* __restrict__ attn,
                            int N, int L) {
    int n = blockIdx.x;
    if (g_flags[n]) return;
    int b = n / N;
    int idx = g_argmin[n];
    int t = threadIdx.x;
    float* row = attn + (size_t)n * N;

    for (int m = t * 4; m < N; m += 256 * 4) {
        float4 v = make_float4(0.f, 0.f, 0.f, 0.f);
        if (idx >= m && idx < m + 4) {
            if (idx == m)     v.x = 1.f;
            if (idx == m + 1) v.y = 1.f;
            if (idx == m + 2) v.z = 1.f;
            if (idx == m + 3) v.w = 1.f;
        }
        if (m + 3 < N) *(float4*)(row + m) = v;
        else for (int q = 0; q < 4 && m + q < N; q++) row[m + q] = (&v.x)[q];
    }
    if (t < L) {
        const float* xpb = g_xp + (size_t)b * N * L;
        h_out[(size_t)n * L + t] = xpb[(size_t)idx * L + t];
    }
}

// ---------- Kernel 5: general fallback (flag-gated; exact fp32 recompute) -------
__global__ void attn_slow_kernel(float* __restrict__ h_out,
                                 float* __restrict__ attn,
                                 int N, int L) {
    int n = blockIdx.x;
    if (g_flags[n] == 0) return;

    extern __shared__ unsigned su[];
    float* sf = (float*)su;
    __shared__ float xq[MAX_L];
    __shared__ float redf[256];
    __shared__ int   warp_tot[8];
    __shared__ int   s_cnt;
    __shared__ int   s_nnz;
    __shared__ int   ilist[1024];
    const int K = 100;

    int b = n / N;
    int diag = n - b * N;
    int t = threadIdx.x;
    int lane = t & 31, w = t >> 5;
    float* row = attn + (size_t)n * N;
    const float* xpb = g_xp + (size_t)b * N * L;

    for (int l = t; l < L; l += 256) xq[l] = xpb[(size_t)diag * L + l];
    __syncthreads();
    for (int m = t; m < N; m += 256) {
        const float* xm = xpb + (size_t)m * L;
        float d = 0.f;
        for (int l = 0; l < L; l++) d += xq[l] * xm[l];
        su[m] = f2key(d);
    }
    __syncthreads();

    unsigned res = 0u;
    for (int bit = 31; bit >= 0; --bit) {
        unsigned cand = res | (1u << bit);
        if (t == 0) s_cnt = 0;
        __syncthreads();
        int c = 0;
        for (int m = t; m < N; m += 256) c += (su[m] >= cand) ? 1 : 0;
#pragma unroll
        for (int o = 16; o; o >>= 1) c += __shfl_down_sync(0xffffffffu, c, o);
        if (lane == 0) atomicAdd(&s_cnt, c);
        __syncthreads();
        if (s_cnt >= K) res = cand;
        __syncthreads();
    }

    if (t == 0) s_cnt = 0;
    __syncthreads();
    {
        int c = 0;
        for (int m = t; m < N; m += 256) c += (su[m] > res) ? 1 : 0;
#pragma unroll
        for (int o = 16; o; o >>= 1) c += __shfl_down_sync(0xffffffffu, c, o);
        if (lane == 0) atomicAdd(&s_cnt, c);
    }
    __syncthreads();
    int need = K - s_cnt;
    __syncthreads();

    int running = 0;
    float vmax = -3.4e38f;
    for (int m0 = 0; m0 < N; m0 += 256) {
        int m = m0 + t;
        bool valid = (m < N);
        unsigned u = valid ? su[m] : 0u;
        bool eq = valid && (u == res);
        unsigned ball = __ballot_sync(0xffffffffu, eq);
        if (lane == 0) warp_tot[w] = __popc(ball);
        __syncthreads();
        int woff = 0, ctot = 0;
#pragma unroll
        for (int i = 0; i < 8; i++) {
            int wt = warp_tot[i];
            ctot += wt;
            if (i < w) woff += wt;
        }
        int rank = running + woff + __popc(ball & ((1u << lane) - 1u));
        if (valid) {
            bool nb = (u > res) || (eq && rank < need) || (m == diag);
            float s = key2f(u);
            float v = nb ? s : (-1e19f * s);
            sf[m] = v;
            vmax = fmaxf(vmax, v);
        }
        running += ctot;
        __syncthreads();
    }

    redf[t] = vmax; __syncthreads();
#pragma unroll
    for (int st = 128; st; st >>= 1) { if (t < st) redf[t] = fmaxf(redf[t], redf[t + st]); __syncthreads(); }
    float M = redf[0]; __syncthreads();

    float lsum = 0.f;
    for (int m = t; m < N; m += 256) {
        float e = expf(sf[m] - M);
        sf[m] = e;
        lsum += e;
    }
    __syncthreads();
    redf[t] = lsum; __syncthreads();
#pragma unroll
    for (int st = 128; st; st >>= 1) { if (t < st) redf[t] += redf[t + st]; __syncthreads(); }
    float inv = 1.0f / redf[0]; __syncthreads();

    if (t == 0) s_nnz = 0;
    __syncthreads();
    for (int m = t; m < N; m += 256) {
        float a = sf[m] * inv;
        sf[m] = a;
        row[m] = a;
        if (a != 0.f) {
            int p = atomicAdd(&s_nnz, 1);
            if (p < 1024) ilist[p] = m;
        }
    }
    __syncthreads();
    int nnz = s_nnz;

    if (t < L) {
        float acc = 0.f;
        if (nnz == 1) {
            int m = ilist[0];
            acc = sf[m] * xpb[(size_t)m * L + t];
        } else {
            for (int m = 0; m < N; m++) {
                float a = sf[m];
                if (a != 0.f) acc += a * xpb[(size_t)m * L + t];
            }
        }
        h_out[(size_t)n * L + t] = acc;
    }
}

// ---------- launch ----------
extern "C" void kernel_launch(void* const* d_in, const int* in_sizes, int n_in,
                              void* d_out, int out_size) {
    const float* x = (const float*)d_in[0];
    const float* W = (const float*)d_in[1];

    int L = (int)(sqrt((double)in_sizes[1]) + 0.5);
    long long BN = in_sizes[0] / L;
    long long N  = (long long)out_size / BN - L;
    int Ni = (int)N;
    int B  = (int)(BN / N);
    int BNi = (int)BN;

    float* h_out = (float*)d_out;
    float* attn  = h_out + (size_t)BN * L;

    proj_kernel<<<(BNi + PROJ_ROWS - 1) / PROJ_ROWS, 256>>>(x, W, BNi, L);

    int nb = (Ni + 127) / 128;
    int tri = nb * (nb + 1) / 2;
    dim3 g2(tri, B);
    score_stats_kernel<<<g2, 256>>>(Ni, L, nb);

    merge_kernel<<<(BNi + 255) / 256, 256>>>(BNi, Ni, nb, 100);

    fill_kernel<<<BNi, 256>>>(h_out, attn, Ni, L);

    size_t smem = (size_t)Ni * sizeof(float);
    attn_slow_kernel<<<BNi, 256, smem>>>(h_out, attn, Ni, L);
}

// round 8
// speedup vs baseline: 1.9794x; 1.9794x over previous
#include <cuda_runtime.h>
#include <cuda_bf16.h>
#include <math.h>
#include <cstdint>

#define MAX_BN 8192
#define MAX_L  256
#define MAX_NB 64
#define XPB_STRIDE 256

__device__ float         g_xp [MAX_BN * MAX_L];       // fp32 projection
__device__ __nv_bfloat16 g_xpb[MAX_BN * XPB_STRIDE];  // bf16, zero-padded cols
__device__ int   g_flags[MAX_BN];
__device__ int   g_argmin[MAX_BN];
__device__ float g_pmin [MAX_BN * MAX_NB];
__device__ float g_pmin2[MAX_BN * MAX_NB];
__device__ float g_pmax [MAX_BN * MAX_NB];
__device__ int   g_pidx [MAX_BN * MAX_NB];

// ---------- helpers ----------
__device__ __forceinline__ unsigned f2key(float f) {
    unsigned u = __float_as_uint(f);
    return (u & 0x80000000u) ? ~u : (u | 0x80000000u);
}
__device__ __forceinline__ float key2f(unsigned k) {
    unsigned u = (k & 0x80000000u) ? (k & 0x7fffffffu) : ~k;
    return __uint_as_float(u);
}
__device__ __forceinline__ void mma_bf16(float* d, const unsigned* a, const unsigned* b) {
    asm volatile(
        "mma.sync.aligned.m16n8k16.row.col.f32.bf16.bf16.f32 "
        "{%0,%1,%2,%3}, {%4,%5,%6,%7}, {%8,%9}, {%0,%1,%2,%3};"
        : "+f"(d[0]), "+f"(d[1]), "+f"(d[2]), "+f"(d[3])
        : "r"(a[0]), "r"(a[1]), "r"(a[2]), "r"(a[3]),
          "r"(b[0]), "r"(b[1]));
}

// ---------- Kernel 1: x_proj = x @ W^T (fp32 + bf16 copies) ----------
#define PROJ_ROWS 8
__global__ void proj_kernel(const float* __restrict__ x,
                            const float* __restrict__ W,
                            int BN, int L) {
    __shared__ float xs[PROJ_ROWS * 256];
    __shared__ float Ws[32][257];
    int n0 = blockIdx.x * PROJ_ROWS;
    int rows = min(PROJ_ROWS, BN - n0);
    int t = threadIdx.x;
    for (int i = t; i < rows * L; i += 256) xs[i] = x[(size_t)n0 * L + i];

    float acc[PROJ_ROWS];
#pragma unroll
    for (int r = 0; r < PROJ_ROWS; r++) acc[r] = 0.f;

    for (int l0 = 0; l0 < L; l0 += 32) {
        int lw = min(32, L - l0);
        __syncthreads();
        for (int idx = t; idx < L * lw; idx += 256) {
            int o = idx / lw, l = idx - o * lw;
            Ws[l][o] = W[(size_t)o * L + l0 + l];
        }
        __syncthreads();
        if (t < L) {
            for (int l = 0; l < lw; l++) {
                float w = Ws[l][t];
#pragma unroll
                for (int r = 0; r < PROJ_ROWS; r++)
                    acc[r] += xs[r * L + l0 + l] * w;
            }
        }
    }
    for (int r = 0; r < rows; r++) {
        if (t < L) {
            g_xp[(size_t)(n0 + r) * L + t] = acc[r];
            g_xpb[(size_t)(n0 + r) * XPB_STRIDE + t] = __float2bfloat16_rn(acc[r]);
        } else {
            g_xpb[(size_t)(n0 + r) * XPB_STRIDE + t] = __float2bfloat16_rn(0.f);
        }
    }
}

// ---------- Kernel 2: bf16 HMMA score GEMM -> per-row strip statistics ----------
// Block = 256 threads = 8 warps (2x4); tile 128x128; warp tile 64x32 via
// m16n8k16 (4 m-tiles x 4 n-tiles); K-chunk = 16 bf16 = 8 packed u32.
__global__ __launch_bounds__(256, 2)
void score_stats_kernel(int N, int L, int nb, int nk) {
    int b = blockIdx.y;
    const __nv_bfloat16* basep = g_xpb + (size_t)b * N * XPB_STRIDE;

    // triangular block mapping (bj >= bi)
    int t = blockIdx.x;
    int bi;
    {
        float fnb = (float)(2 * nb + 1);
        int est = (int)((fnb - sqrtf(fnb * fnb - 8.0f * (float)t)) * 0.5f);
        if (est < 0) est = 0;
        if (est >= nb) est = nb - 1;
        bi = est;
        while (bi > 0 && (bi * nb - bi * (bi - 1) / 2) > t) bi--;
        while (((bi + 1) * nb - (bi + 1) * bi / 2) <= t) bi++;
    }
    int bj = bi + (t - (bi * nb - bi * (bi - 1) / 2));
    int i0 = bi * 128, j0 = bj * 128;

    // As[kk][row]: packed bf16x2 for k = 2kk, 2kk+1 within the 16-wide chunk
    __shared__ __align__(16) unsigned As[2][8][136];
    __shared__ __align__(16) unsigned Bs[2][8][136];
    __shared__ float sred[128][17];
    __shared__ int   sredi[128][17];

    int tid  = threadIdx.x;
    int lane = tid & 31, wid = tid >> 5;
    int wm = wid >> 2, wn = wid & 3;      // warp grid 2 x 4
    int gid = lane >> 2, tig = lane & 3;  // fragment coords
    int lr = tid >> 1;                    // 0..127 row for smem fill
    int lh = (tid & 1) * 4;               // pair-offset 0/4 for smem fill

    float acc[4][4][4] = {};

    // bounds-safe uint4 load: 8 bf16 = 4 packed pairs from row (i/j), chunk c
    auto ld8 = [&](int row, int c) -> uint4 {
        if (row < N) {
            const uint4* p = (const uint4*)(basep + (size_t)row * XPB_STRIDE);
            return p[2 * c + (tid & 1)];
        }
        return make_uint4(0u, 0u, 0u, 0u);
    };

    // prefetch chunk 0
    {
        uint4 av = ld8(i0 + lr, 0);
        uint4 bv = ld8(j0 + lr, 0);
        As[0][lh + 0][lr] = av.x; As[0][lh + 1][lr] = av.y;
        As[0][lh + 2][lr] = av.z; As[0][lh + 3][lr] = av.w;
        Bs[0][lh + 0][lr] = bv.x; Bs[0][lh + 1][lr] = bv.y;
        Bs[0][lh + 2][lr] = bv.z; Bs[0][lh + 3][lr] = bv.w;
    }
    __syncthreads();

    int buf = 0;
    for (int kc = 0; kc < nk; kc++) {
        uint4 an, bn;
        bool has = (kc + 1 < nk);
        if (has) {
            an = ld8(i0 + lr, kc + 1);
            bn = ld8(j0 + lr, kc + 1);
        }

        // B fragments: b0 = pairs k(2tig,2tig+1), b1 = pairs k(2tig+8,2tig+9)
        unsigned bfr[4][2];
#pragma unroll
        for (int nt = 0; nt < 4; nt++) {
            int col = wn * 32 + nt * 8 + gid;
            bfr[nt][0] = Bs[buf][tig][col];
            bfr[nt][1] = Bs[buf][tig + 4][col];
        }
#pragma unroll
        for (int mt = 0; mt < 4; mt++) {
            int row = wm * 64 + mt * 16 + gid;
            unsigned afr[4];
            afr[0] = As[buf][tig][row];
            afr[1] = As[buf][tig][row + 8];
            afr[2] = As[buf][tig + 4][row];
            afr[3] = As[buf][tig + 4][row + 8];
#pragma unroll
            for (int nt = 0; nt < 4; nt++)
                mma_bf16(acc[mt][nt], afr, bfr[nt]);
        }

        if (has) {
            int nb2 = buf ^ 1;
            As[nb2][lh + 0][lr] = an.x; As[nb2][lh + 1][lr] = an.y;
            As[nb2][lh + 2][lr] = an.z; As[nb2][lh + 3][lr] = an.w;
            Bs[nb2][lh + 0][lr] = bn.x; Bs[nb2][lh + 1][lr] = bn.y;
            Bs[nb2][lh + 2][lr] = bn.z; Bs[nb2][lh + 3][lr] = bn.w;
        }
        __syncthreads();
        buf ^= 1;
    }

    const float INF = 3.4e38f;
    // element coords: row(mt,hh) = wm*64 + mt*16 + gid + 8*hh
    //                 col(nt,r)  = wn*32 + nt*8 + 2*tig + r
    //                 value      = acc[mt][nt][2*hh + r]

    float rm1 = INF, rm2 = INF, rmx = -INF;
    int ridx = 0x7fffffff;

    // =========== Phase A: stats over j-cols for each i-row ==========
#pragma unroll
    for (int mt = 0; mt < 4; mt++)
#pragma unroll
        for (int hh = 0; hh < 2; hh++) {
            int lrow = wm * 64 + mt * 16 + gid + 8 * hh;
            float m1 = INF; int idx = 0x7fffffff;
#pragma unroll
            for (int nt = 0; nt < 4; nt++)
#pragma unroll
                for (int r = 0; r < 2; r++) {
                    int col = j0 + wn * 32 + nt * 8 + 2 * tig + r;
                    float v = acc[mt][nt][2 * hh + r];
                    if (col < N && v < m1) { m1 = v; idx = col; }
                }
            sred[lrow][wn * 4 + tig] = m1;
            sredi[lrow][wn * 4 + tig] = idx;
        }
    __syncthreads();
    float rm2a = INF;
    if (tid < 128) {
        rm1 = INF; ridx = 0x7fffffff;
#pragma unroll
        for (int q = 0; q < 16; q++) {
            float v = sred[tid][q]; int ix = sredi[tid][q];
            if (v < rm1) { rm2a = rm1; rm1 = v; ridx = ix; }
            else if (v == rm1) { rm2a = v; ridx = min(ridx, ix); }
            else if (v < rm2a) rm2a = v;
        }
    }
    __syncthreads();
#pragma unroll
    for (int mt = 0; mt < 4; mt++)
#pragma unroll
        for (int hh = 0; hh < 2; hh++) {
            int lrow = wm * 64 + mt * 16 + gid + 8 * hh;
            float m1 = INF, m2 = INF;
#pragma unroll
            for (int nt = 0; nt < 4; nt++)
#pragma unroll
                for (int r = 0; r < 2; r++) {
                    int col = j0 + wn * 32 + nt * 8 + 2 * tig + r;
                    float v = acc[mt][nt][2 * hh + r];
                    if (col < N) {
                        if (v < m1) { m2 = m1; m1 = v; }
                        else if (v < m2) m2 = v;
                    }
                }
            sred[lrow][wn * 4 + tig] = m2;
        }
    __syncthreads();
    if (tid < 128) {
        rm2 = rm2a;
#pragma unroll
        for (int q = 0; q < 16; q++) rm2 = fminf(rm2, sred[tid][q]);
    }
    __syncthreads();
#pragma unroll
    for (int mt = 0; mt < 4; mt++)
#pragma unroll
        for (int hh = 0; hh < 2; hh++) {
            int lrow = wm * 64 + mt * 16 + gid + 8 * hh;
            float mx = -INF;
#pragma unroll
            for (int nt = 0; nt < 4; nt++)
#pragma unroll
                for (int r = 0; r < 2; r++) {
                    int col = j0 + wn * 32 + nt * 8 + 2 * tig + r;
                    float v = acc[mt][nt][2 * hh + r];
                    if (col < N) mx = fmaxf(mx, v);
                }
            sred[lrow][wn * 4 + tig] = mx;
        }
    __syncthreads();
    if (tid < 128) {
        rmx = -INF;
#pragma unroll
        for (int q = 0; q < 16; q++) rmx = fmaxf(rmx, sred[tid][q]);
        if (i0 + tid < N) {
            size_t o = (size_t)(b * N + i0 + tid) * MAX_NB + bj;
            g_pmin[o] = rm1; g_pmin2[o] = rm2; g_pmax[o] = rmx; g_pidx[o] = ridx;
        }
    }

    // =========== Phase B (mirror): stats over i-rows for each j-col ==========
    if (bi != bj) {
        __syncthreads();
#pragma unroll
        for (int nt = 0; nt < 4; nt++)
#pragma unroll
            for (int r = 0; r < 2; r++) {
                int lcol = wn * 32 + nt * 8 + 2 * tig + r;
                float m1 = INF; int idx = 0x7fffffff;
#pragma unroll
                for (int mt = 0; mt < 4; mt++)
#pragma unroll
                    for (int hh = 0; hh < 2; hh++) {
                        int grow = i0 + wm * 64 + mt * 16 + gid + 8 * hh;
                        float v = acc[mt][nt][2 * hh + r];
                        if (grow < N && v < m1) { m1 = v; idx = grow; }
                    }
                sred[lcol][wm * 8 + gid] = m1;
                sredi[lcol][wm * 8 + gid] = idx;
            }
        __syncthreads();
        rm2a = INF;
        if (tid < 128) {
            rm1 = INF; ridx = 0x7fffffff;
#pragma unroll
            for (int q = 0; q < 16; q++) {
                float v = sred[tid][q]; int ix = sredi[tid][q];
                if (v < rm1) { rm2a = rm1; rm1 = v; ridx = ix; }
                else if (v == rm1) { rm2a = v; ridx = min(ridx, ix); }
                else if (v < rm2a) rm2a = v;
            }
        }
        __syncthreads();
#pragma unroll
        for (int nt = 0; nt < 4; nt++)
#pragma unroll
            for (int r = 0; r < 2; r++) {
                int lcol = wn * 32 + nt * 8 + 2 * tig + r;
                float m1 = INF, m2 = INF;
#pragma unroll
                for (int mt = 0; mt < 4; mt++)
#pragma unroll
                    for (int hh = 0; hh < 2; hh++) {
                        int grow = i0 + wm * 64 + mt * 16 + gid + 8 * hh;
                        float v = acc[mt][nt][2 * hh + r];
                        if (grow < N) {
                            if (v < m1) { m2 = m1; m1 = v; }
                            else if (v < m2) m2 = v;
                        }
                    }
                sred[lcol][wm * 8 + gid] = m2;
            }
        __syncthreads();
        if (tid < 128) {
            rm2 = rm2a;
#pragma unroll
            for (int q = 0; q < 16; q++) rm2 = fminf(rm2, sred[tid][q]);
        }
        __syncthreads();
#pragma unroll
        for (int nt = 0; nt < 4; nt++)
#pragma unroll
            for (int r = 0; r < 2; r++) {
                int lcol = wn * 32 + nt * 8 + 2 * tig + r;
                float mx = -INF;
#pragma unroll
                for (int mt = 0; mt < 4; mt++)
#pragma unroll
                    for (int hh = 0; hh < 2; hh++) {
                        int grow = i0 + wm * 64 + mt * 16 + gid + 8 * hh;
                        float v = acc[mt][nt][2 * hh + r];
                        if (grow < N) mx = fmaxf(mx, v);
                    }
                sred[lcol][wm * 8 + gid] = mx;
            }
        __syncthreads();
        if (tid < 128) {
            rmx = -INF;
#pragma unroll
            for (int q = 0; q < 16; q++) rmx = fmaxf(rmx, sred[tid][q]);
            if (j0 + tid < N) {
                size_t o = (size_t)(b * N + j0 + tid) * MAX_NB + bi;
                g_pmin[o] = rm1; g_pmin2[o] = rm2; g_pmax[o] = rmx; g_pidx[o] = ridx;
            }
        }
    }
}

// ---------- Kernel 3: merge strip stats -> argmin + guard flag per row ----------
__global__ void merge_kernel(int BN, int N, int nb, int K) {
    int n = blockIdx.x * 256 + threadIdx.x;
    if (n >= BN) return;
    const float INF = 3.4e38f;
    float m1 = INF, m2 = INF, mx = -INF;
    int idx = 0x7fffffff;
    size_t base = (size_t)n * MAX_NB;
    for (int s = 0; s < nb; s++) {
        float pm1 = g_pmin[base + s];
        float pm2 = g_pmin2[base + s];
        float px  = g_pmax[base + s];
        int   pi  = g_pidx[base + s];
        mx = fmaxf(mx, px);
        if (pm1 < m1) {
            m2 = fminf(m1, pm2);
            m1 = pm1; idx = pi;
        } else if (pm1 == m1) {
            m2 = m1;
            idx = min(idx, pi);
        } else {
            m2 = fminf(m2, pm1);
        }
    }
    // guards: one-hot exactness + bf16-noise margin on the argmin gap
    bool ok = (m1 < -1.0f)
           && (-m1 > (mx + 256.f) * 1e-19f)
           && (m2 - m1 > 0.6f)
           && (N > K + 1);
    g_flags[n]  = ok ? 0 : 1;
    g_argmin[n] = idx;
}

// ---------- Kernel 4: one-hot attention fill + h gather (write-only) ------------
__global__ void fill_kernel(float* __restrict__ h_out,
                            float* __restrict__ attn,
                            int N, int L) {
    int n = blockIdx.x;
    if (g_flags[n]) return;
    int b = n / N;
    int idx = g_argmin[n];
    int t = threadIdx.x;
    float* row = attn + (size_t)n * N;

    for (int m = t * 4; m < N; m += 256 * 4) {
        float4 v = make_float4(0.f, 0.f, 0.f, 0.f);
        if (idx >= m && idx < m + 4) {
            if (idx == m)     v.x = 1.f;
            if (idx == m + 1) v.y = 1.f;
            if (idx == m + 2) v.z = 1.f;
            if (idx == m + 3) v.w = 1.f;
        }
        if (m + 3 < N) *(float4*)(row + m) = v;
        else for (int q = 0; q < 4 && m + q < N; q++) row[m + q] = (&v.x)[q];
    }
    if (t < L) {
        const float* xpb = g_xp + (size_t)b * N * L;
        h_out[(size_t)n * L + t] = xpb[(size_t)idx * L + t];
    }
}

// ---------- Kernel 5: general fallback (flag-gated; exact fp32 recompute) -------
__global__ void attn_slow_kernel(float* __restrict__ h_out,
                                 float* __restrict__ attn,
                                 int N, int L) {
    int n = blockIdx.x;
    if (g_flags[n] == 0) return;

    extern __shared__ unsigned su[];
    float* sf = (float*)su;
    __shared__ __align__(16) float xq[MAX_L];
    __shared__ float redf[256];
    __shared__ int   warp_tot[8];
    __shared__ int   s_cnt;
    __shared__ int   s_nnz;
    __shared__ int   ilist[1024];
    const int K = 100;

    int b = n / N;
    int diag = n - b * N;
    int t = threadIdx.x;
    int lane = t & 31, w = t >> 5;
    float* row = attn + (size_t)n * N;
    const float* xpb = g_xp + (size_t)b * N * L;

    for (int l = t; l < L; l += 256) xq[l] = xpb[(size_t)diag * L + l];
    __syncthreads();

    if ((L & 3) == 0) {
        int L4 = L >> 2;
        const float4* xq4 = (const float4*)xq;
        for (int m = t; m < N; m += 256) {
            const float4* xm4 = (const float4*)(xpb + (size_t)m * L);
            float d = 0.f;
            for (int l = 0; l < L4; l++) {
                float4 a = xq4[l], bb = xm4[l];
                d += a.x * bb.x + a.y * bb.y + a.z * bb.z + a.w * bb.w;
            }
            su[m] = f2key(d);
        }
    } else {
        for (int m = t; m < N; m += 256) {
            const float* xm = xpb + (size_t)m * L;
            float d = 0.f;
            for (int l = 0; l < L; l++) d += xq[l] * xm[l];
            su[m] = f2key(d);
        }
    }
    __syncthreads();

    unsigned res = 0u;
    for (int bit = 31; bit >= 0; --bit) {
        unsigned cand = res | (1u << bit);
        if (t == 0) s_cnt = 0;
        __syncthreads();
        int c = 0;
        for (int m = t; m < N; m += 256) c += (su[m] >= cand) ? 1 : 0;
#pragma unroll
        for (int o = 16; o; o >>= 1) c += __shfl_down_sync(0xffffffffu, c, o);
        if (lane == 0) atomicAdd(&s_cnt, c);
        __syncthreads();
        if (s_cnt >= K) res = cand;
        __syncthreads();
    }

    if (t == 0) s_cnt = 0;
    __syncthreads();
    {
        int c = 0;
        for (int m = t; m < N; m += 256) c += (su[m] > res) ? 1 : 0;
#pragma unroll
        for (int o = 16; o; o >>= 1) c += __shfl_down_sync(0xffffffffu, c, o);
        if (lane == 0) atomicAdd(&s_cnt, c);
    }
    __syncthreads();
    int need = K - s_cnt;
    __syncthreads();

    int running = 0;
    float vmax = -3.4e38f;
    for (int m0 = 0; m0 < N; m0 += 256) {
        int m = m0 + t;
        bool valid = (m < N);
        unsigned u = valid ? su[m] : 0u;
        bool eq = valid && (u == res);
        unsigned ball = __ballot_sync(0xffffffffu, eq);
        if (lane == 0) warp_tot[w] = __popc(ball);
        __syncthreads();
        int woff = 0, ctot = 0;
#pragma unroll
        for (int i = 0; i < 8; i++) {
            int wt = warp_tot[i];
            ctot += wt;
            if (i < w) woff += wt;
        }
        int rank = running + woff + __popc(ball & ((1u << lane) - 1u));
        if (valid) {
            bool nb = (u > res) || (eq && rank < need) || (m == diag);
            float s = key2f(u);
            float v = nb ? s : (-1e19f * s);
            sf[m] = v;
            vmax = fmaxf(vmax, v);
        }
        running += ctot;
        __syncthreads();
    }

    redf[t] = vmax; __syncthreads();
#pragma unroll
    for (int st = 128; st; st >>= 1) { if (t < st) redf[t] = fmaxf(redf[t], redf[t + st]); __syncthreads(); }
    float M = redf[0]; __syncthreads();

    float lsum = 0.f;
    for (int m = t; m < N; m += 256) {
        float e = expf(sf[m] - M);
        sf[m] = e;
        lsum += e;
    }
    __syncthreads();
    redf[t] = lsum; __syncthreads();
#pragma unroll
    for (int st = 128; st; st >>= 1) { if (t < st) redf[t] += redf[t + st]; __syncthreads(); }
    float inv = 1.0f / redf[0]; __syncthreads();

    if (t == 0) s_nnz = 0;
    __syncthreads();
    for (int m = t; m < N; m += 256) {
        float a = sf[m] * inv;
        sf[m] = a;
        row[m] = a;
        if (a != 0.f) {
            int p = atomicAdd(&s_nnz, 1);
            if (p < 1024) ilist[p] = m;
        }
    }
    __syncthreads();
    int nnz = s_nnz;

    if (t < L) {
        float acc = 0.f;
        if (nnz == 1) {
            int m = ilist[0];
            acc = sf[m] * xpb[(size_t)m * L + t];
        } else {
            for (int m = 0; m < N; m++) {
                float a = sf[m];
                if (a != 0.f) acc += a * xpb[(size_t)m * L + t];
            }
        }
        h_out[(size_t)n * L + t] = acc;
    }
}

// ---------- launch ----------
extern "C" void kernel_launch(void* const* d_in, const int* in_sizes, int n_in,
                              void* d_out, int out_size) {
    const float* x = (const float*)d_in[0];
    const float* W = (const float*)d_in[1];

    int L = (int)(sqrt((double)in_sizes[1]) + 0.5);
    long long BN = in_sizes[0] / L;
    long long N  = (long long)out_size / BN - L;
    int Ni = (int)N;
    int B  = (int)(BN / N);
    int BNi = (int)BN;
    int nk = (L + 15) / 16;   // K-chunks of 16 bf16

    float* h_out = (float*)d_out;
    float* attn  = h_out + (size_t)BN * L;

    proj_kernel<<<(BNi + PROJ_ROWS - 1) / PROJ_ROWS, 256>>>(x, W, BNi, L);

    int nb = (Ni + 127) / 128;
    int tri = nb * (nb + 1) / 2;
    dim3 g2(tri, B);
    score_stats_kernel<<<g2, 256>>>(Ni, L, nb, nk);

    merge_kernel<<<(BNi + 255) / 256, 256>>>(BNi, Ni, nb, 100);

    fill_kernel<<<BNi, 256>>>(h_out, attn, Ni, L);

    size_t smem = (size_t)Ni * sizeof(float);
    attn_slow_kernel<<<BNi, 256, smem>>>(h_out, attn, Ni, L);
}

// round 9
// speedup vs baseline: 2.8206x; 1.4250x over previous
#include <cuda_runtime.h>
#include <cuda_fp16.h>
#include <math.h>
#include <cstdint>

#define MAX_BN 8192
#define MAX_L  256
#define MAX_NB 64
#define XPH_STRIDE 256   // halves per row (zero-padded)

__device__ float  g_xp [MAX_BN * MAX_L];        // fp32 projection
__device__ __half g_xph[MAX_BN * XPH_STRIDE];   // fp16 copy, zero-padded
__device__ int    g_flags[MAX_BN];
__device__ int    g_argmin[MAX_BN];
__device__ float  g_pmin [MAX_BN * MAX_NB];
__device__ float  g_pmin2[MAX_BN * MAX_NB];
__device__ float  g_pmax [MAX_BN * MAX_NB];
__device__ int    g_pidx [MAX_BN * MAX_NB];
__device__ int    g_list[MAX_BN];
__device__ int    g_cnt[64];

// ---------- helpers ----------
__device__ __forceinline__ unsigned f2key(float f) {
    unsigned u = __float_as_uint(f);
    return (u & 0x80000000u) ? ~u : (u | 0x80000000u);
}
__device__ __forceinline__ float key2f(unsigned k) {
    unsigned u = (k & 0x80000000u) ? (k & 0x7fffffffu) : ~k;
    return __uint_as_float(u);
}

__global__ void init_kernel() {
    if (threadIdx.x < 64) g_cnt[threadIdx.x] = 0;
}

// ---------- Kernel 1: x_proj = x @ W^T (fp32 + fp16 copies) ----------
#define PROJ_ROWS 8
__global__ void proj_kernel(const float* __restrict__ x,
                            const float* __restrict__ W,
                            int BN, int L) {
    __shared__ float xs[PROJ_ROWS * 256];
    __shared__ float Ws[32][257];
    int n0 = blockIdx.x * PROJ_ROWS;
    int rows = min(PROJ_ROWS, BN - n0);
    int t = threadIdx.x;
    for (int i = t; i < rows * L; i += 256) xs[i] = x[(size_t)n0 * L + i];

    float acc[PROJ_ROWS];
#pragma unroll
    for (int r = 0; r < PROJ_ROWS; r++) acc[r] = 0.f;

    for (int l0 = 0; l0 < L; l0 += 32) {
        int lw = min(32, L - l0);
        __syncthreads();
        for (int idx = t; idx < L * lw; idx += 256) {
            int o = idx / lw, l = idx - o * lw;
            Ws[l][o] = W[(size_t)o * L + l0 + l];
        }
        __syncthreads();
        if (t < L) {
            for (int l = 0; l < lw; l++) {
                float w = Ws[l][t];
#pragma unroll
                for (int r = 0; r < PROJ_ROWS; r++)
                    acc[r] += xs[r * L + l0 + l] * w;
            }
        }
    }
    for (int r = 0; r < rows; r++) {
        if (t < L) {
            g_xp[(size_t)(n0 + r) * L + t] = acc[r];
            g_xph[(size_t)(n0 + r) * XPH_STRIDE + t] = __float2half_rn(acc[r]);
        } else {
            g_xph[(size_t)(n0 + r) * XPH_STRIDE + t] = __float2half_rn(0.f);
        }
    }
}

// ---------- Kernel 2: HFMA2 (fp16x2) score GEMM -> per-row strip statistics ----
// 256 threads (tx=tid&15 cols, ty=tid>>4 rows), 128x128 tile, 8x8 per thread.
// K processed in chunks of 32 (16 half2 pair-steps); half2 accs folded to fp32
// per chunk. Triangular blocks + mirrored stats (phase B).
#define AS(buf,kp,row) (((__half2*)pool)[((buf)*16 + (kp))*136 + (row)])
#define BS(buf,kp,row) (((__half2*)pool)[4352 + ((buf)*16 + (kp))*136 + (row)])
#define SRED(r,q)  (((float*)pool)[(r)*17 + (q)])
#define SREDI(r,q) (((int*)(pool + 8704))[(r)*17 + (q)])

__global__ __launch_bounds__(256, 1)
void score_h2_kernel(int N, int L, int nb, int nkc) {
    __shared__ __align__(16) char pool[2 * 2 * 16 * 136 * 4];  // 34816 B

    int b = blockIdx.y;
    const __half* xph = g_xph + (size_t)b * N * XPH_STRIDE;

    // triangular block mapping (bj >= bi)
    int t = blockIdx.x;
    int bi;
    {
        float fnb = (float)(2 * nb + 1);
        int est = (int)((fnb - sqrtf(fnb * fnb - 8.0f * (float)t)) * 0.5f);
        if (est < 0) est = 0;
        if (est >= nb) est = nb - 1;
        bi = est;
        while (bi > 0 && (bi * nb - bi * (bi - 1) / 2) > t) bi--;
        while (((bi + 1) * nb - (bi + 1) * bi / 2) <= t) bi++;
    }
    int bj = bi + (t - (bi * nb - bi * (bi - 1) / 2));
    int i0 = bi * 128, j0 = bj * 128;

    int tid = threadIdx.x;
    int tx = tid & 15, ty = tid >> 4;
    int lr = tid >> 1;          // row 0..127 for fills
    int lq = tid & 1;           // which uint4 pair-group

    const __half2 HZ = __float2half2_rn(0.f);
    float   acc [8][8];
    __half2 acc2[8][8];
#pragma unroll
    for (int a = 0; a < 8; a++)
#pragma unroll
        for (int c = 0; c < 8; c++) { acc[a][c] = 0.f; acc2[a][c] = HZ; }

    const uint4 Z4 = make_uint4(0u, 0u, 0u, 0u);
    // load chunk kc (16 half2) for a 128-row panel: 2 uint4 per thread per matrix
    auto ldrow = [&](int grow, int kc, uint4& v0, uint4& v1) {
        if (grow < N) {
            const uint4* p = (const uint4*)(xph + (size_t)grow * XPH_STRIDE);
            v0 = p[kc * 4 + lq];
            v1 = p[kc * 4 + lq + 2];
        } else { v0 = Z4; v1 = Z4; }
    };
    auto stA = [&](int buf, uint4 v0, uint4 v1) {
        AS(buf, lq * 4 + 0, lr) = *(__half2*)&v0.x;
        AS(buf, lq * 4 + 1, lr) = *(__half2*)&v0.y;
        AS(buf, lq * 4 + 2, lr) = *(__half2*)&v0.z;
        AS(buf, lq * 4 + 3, lr) = *(__half2*)&v0.w;
        AS(buf, lq * 4 + 8, lr) = *(__half2*)&v1.x;
        AS(buf, lq * 4 + 9, lr) = *(__half2*)&v1.y;
        AS(buf, lq * 4 + 10, lr) = *(__half2*)&v1.z;
        AS(buf, lq * 4 + 11, lr) = *(__half2*)&v1.w;
    };
    auto stB = [&](int buf, uint4 v0, uint4 v1) {
        BS(buf, lq * 4 + 0, lr) = *(__half2*)&v0.x;
        BS(buf, lq * 4 + 1, lr) = *(__half2*)&v0.y;
        BS(buf, lq * 4 + 2, lr) = *(__half2*)&v0.z;
        BS(buf, lq * 4 + 3, lr) = *(__half2*)&v0.w;
        BS(buf, lq * 4 + 8, lr) = *(__half2*)&v1.x;
        BS(buf, lq * 4 + 9, lr) = *(__half2*)&v1.y;
        BS(buf, lq * 4 + 10, lr) = *(__half2*)&v1.z;
        BS(buf, lq * 4 + 11, lr) = *(__half2*)&v1.w;
    };

    {
        uint4 a0, a1, b0, b1;
        ldrow(i0 + lr, 0, a0, a1);
        ldrow(j0 + lr, 0, b0, b1);
        stA(0, a0, a1); stB(0, b0, b1);
    }
    __syncthreads();

    int buf = 0;
    for (int kc = 0; kc < nkc; kc++) {
        uint4 a0, a1, b0, b1;
        bool has = (kc + 1 < nkc);
        if (has) {
            ldrow(i0 + lr, kc + 1, a0, a1);
            ldrow(j0 + lr, kc + 1, b0, b1);
        }
#pragma unroll
        for (int kp = 0; kp < 16; kp++) {
            __half2 ha[8], hb[8];
            *(uint4*)&ha[0] = *(const uint4*)&AS(buf, kp, ty * 8);
            *(uint4*)&ha[4] = *(const uint4*)&AS(buf, kp, ty * 8 + 4);
            *(uint4*)&hb[0] = *(const uint4*)&BS(buf, kp, tx * 8);
            *(uint4*)&hb[4] = *(const uint4*)&BS(buf, kp, tx * 8 + 4);
#pragma unroll
            for (int a = 0; a < 8; a++)
#pragma unroll
                for (int c = 0; c < 8; c++)
                    acc2[a][c] = __hfma2(ha[a], hb[c], acc2[a][c]);
        }
        // fold half2 accumulators into fp32 (every 32 k)
#pragma unroll
        for (int a = 0; a < 8; a++)
#pragma unroll
            for (int c = 0; c < 8; c++) {
                float2 f = __half22float2(acc2[a][c]);
                acc[a][c] += f.x + f.y;
                acc2[a][c] = HZ;
            }
        if (has) { stA(buf ^ 1, a0, a1); stB(buf ^ 1, b0, b1); }
        __syncthreads();
        buf ^= 1;
    }

    const float INF = 3.4e38f;

    // ===== Phase A: stats per i-row over the 128 j-cols =====
    float rm1 = INF, rm2a = INF, rm2 = INF, rmx = -INF;
    int ridx = 0x7fffffff;
#pragma unroll
    for (int a = 0; a < 8; a++) {
        int lrow = ty * 8 + a;
        float m1 = INF; int idx = 0x7fffffff;
#pragma unroll
        for (int c = 0; c < 8; c++) {
            int col = j0 + tx * 8 + c;
            float v = acc[a][c];
            if (col < N && v < m1) { m1 = v; idx = col; }
        }
        SRED(lrow, tx) = m1; SREDI(lrow, tx) = idx;
    }
    __syncthreads();
    if (tid < 128) {
#pragma unroll
        for (int q = 0; q < 16; q++) {
            float v = SRED(tid, q); int ix = SREDI(tid, q);
            if (v < rm1) { rm2a = rm1; rm1 = v; ridx = ix; }
            else if (v == rm1) { rm2a = v; ridx = min(ridx, ix); }
            else if (v < rm2a) rm2a = v;
        }
    }
    __syncthreads();
#pragma unroll
    for (int a = 0; a < 8; a++) {
        int lrow = ty * 8 + a;
        float m1 = INF, m2 = INF;
#pragma unroll
        for (int c = 0; c < 8; c++) {
            int col = j0 + tx * 8 + c;
            float v = acc[a][c];
            if (col < N) {
                if (v < m1) { m2 = m1; m1 = v; }
                else if (v < m2) m2 = v;
            }
        }
        SRED(lrow, tx) = m2;
    }
    __syncthreads();
    if (tid < 128) {
        rm2 = rm2a;
#pragma unroll
        for (int q = 0; q < 16; q++) rm2 = fminf(rm2, SRED(tid, q));
    }
    __syncthreads();
#pragma unroll
    for (int a = 0; a < 8; a++) {
        int lrow = ty * 8 + a;
        float mx = -INF;
#pragma unroll
        for (int c = 0; c < 8; c++) {
            int col = j0 + tx * 8 + c;
            float v = acc[a][c];
            if (col < N) mx = fmaxf(mx, v);
        }
        SRED(lrow, tx) = mx;
    }
    __syncthreads();
    if (tid < 128) {
        rmx = -INF;
#pragma unroll
        for (int q = 0; q < 16; q++) rmx = fmaxf(rmx, SRED(tid, q));
        if (i0 + tid < N) {
            size_t o = (size_t)((size_t)b * N + i0 + tid) * MAX_NB + bj;
            g_pmin[o] = rm1; g_pmin2[o] = rm2; g_pmax[o] = rmx; g_pidx[o] = ridx;
        }
    }

    // ===== Phase B (mirror): stats per j-col over the 128 i-rows =====
    if (bi != bj) {
        __syncthreads();
        rm1 = INF; rm2a = INF; rm2 = INF; rmx = -INF; ridx = 0x7fffffff;
#pragma unroll
        for (int c = 0; c < 8; c++) {
            int lcol = tx * 8 + c;
            float m1 = INF; int idx = 0x7fffffff;
#pragma unroll
            for (int a = 0; a < 8; a++) {
                int grow = i0 + ty * 8 + a;
                float v = acc[a][c];
                if (grow < N && v < m1) { m1 = v; idx = grow; }
            }
            SRED(lcol, ty) = m1; SREDI(lcol, ty) = idx;
        }
        __syncthreads();
        if (tid < 128) {
#pragma unroll
            for (int q = 0; q < 16; q++) {
                float v = SRED(tid, q); int ix = SREDI(tid, q);
                if (v < rm1) { rm2a = rm1; rm1 = v; ridx = ix; }
                else if (v == rm1) { rm2a = v; ridx = min(ridx, ix); }
                else if (v < rm2a) rm2a = v;
            }
        }
        __syncthreads();
#pragma unroll
        for (int c = 0; c < 8; c++) {
            int lcol = tx * 8 + c;
            float m1 = INF, m2 = INF;
#pragma unroll
            for (int a = 0; a < 8; a++) {
                int grow = i0 + ty * 8 + a;
                float v = acc[a][c];
                if (grow < N) {
                    if (v < m1) { m2 = m1; m1 = v; }
                    else if (v < m2) m2 = v;
                }
            }
            SRED(lcol, ty) = m2;
        }
        __syncthreads();
        if (tid < 128) {
            rm2 = rm2a;
#pragma unroll
            for (int q = 0; q < 16; q++) rm2 = fminf(rm2, SRED(tid, q));
        }
        __syncthreads();
#pragma unroll
        for (int c = 0; c < 8; c++) {
            int lcol = tx * 8 + c;
            float mx = -INF;
#pragma unroll
            for (int a = 0; a < 8; a++) {
                int grow = i0 + ty * 8 + a;
                float v = acc[a][c];
                if (grow < N) mx = fmaxf(mx, v);
            }
            SRED(lcol, ty) = mx;
        }
        __syncthreads();
        if (tid < 128) {
            rmx = -INF;
#pragma unroll
            for (int q = 0; q < 16; q++) rmx = fmaxf(rmx, SRED(tid, q));
            if (j0 + tid < N) {
                size_t o = (size_t)((size_t)b * N + j0 + tid) * MAX_NB + bi;
                g_pmin[o] = rm1; g_pmin2[o] = rm2; g_pmax[o] = rmx; g_pidx[o] = ridx;
            }
        }
    }
}

// ---------- Kernel 3: merge approx strips -> certify or enqueue for refine -----
__global__ void merge1_kernel(int BN, int N, int nb, int K) {
    int n = blockIdx.x * 256 + threadIdx.x;
    if (n >= BN) return;
    const float INF = 3.4e38f;
    float m1 = INF, m2 = INF, mx = -INF;
    int idx = 0x7fffffff;
    size_t base = (size_t)n * MAX_NB;
    for (int s = 0; s < nb; s++) {
        float pm1 = g_pmin[base + s];
        float pm2 = g_pmin2[base + s];
        float px  = g_pmax[base + s];
        int   pi  = g_pidx[base + s];
        mx = fmaxf(mx, px);
        if (pm1 < m1) { m2 = fminf(m1, pm2); m1 = pm1; idx = pi; }
        else if (pm1 == m1) { m2 = m1; idx = min(idx, pi); }
        else { m2 = fminf(m2, pm1); }
    }
    // fp16-noise certified one-hot guard (gap >> 8 sigma of h2 rounding)
    bool ok = (m1 < -1.0f)
           && (-m1 > (mx + 256.f) * 1e-19f)
           && (m2 - m1 > 0.5f)
           && (N > K + 1);
    if (ok) {
        g_flags[n] = 0;
        g_argmin[n] = idx;
    } else {
        g_flags[n] = 1;
        int b = n / N, r = n - b * N;
        int p = atomicAdd(&g_cnt[b], 1);
        g_list[(size_t)b * N + p] = r;
    }
}

// ---------- bounds-safe float4 load (fp32) ----------
__device__ __forceinline__ float4 ldxp4(const float* __restrict__ base,
                                        long long row, int k, int N, int L) {
    float4 v = make_float4(0.f, 0.f, 0.f, 0.f);
    if (row >= 0 && row < N) {
        const float* p = base + (size_t)row * L + k;
        if (k + 3 < L) {
            if ((((unsigned long long)(uintptr_t)p) & 15ull) == 0)
                v = *(const float4*)p;
            else { v.x = p[0]; v.y = p[1]; v.z = p[2]; v.w = p[3]; }
        } else {
            if (k     < L) v.x = p[0];
            if (k + 1 < L) v.y = p[1];
            if (k + 2 < L) v.z = p[2];
        }
    }
    return v;
}

// ---------- Kernel 4: fp32 refine GEMM over gathered flagged rows ---------------
__global__ __launch_bounds__(256, 2)
void refine_kernel(int N, int L, int nb) {
    int b  = blockIdx.z;
    int ct = blockIdx.x;     // column tile
    int rt = blockIdx.y;     // list tile
    int cnt = g_cnt[b];
    if (rt * 128 >= cnt) return;

    __shared__ __align__(16) float As[2][8][136];
    __shared__ __align__(16) float Bs[2][8][136];
    __shared__ float sred[128][17];
    __shared__ int   sredi[128][17];
    __shared__ int   rowmap[128];

    int tid = threadIdx.x;
    if (tid < 128)
        rowmap[tid] = (rt * 128 + tid < cnt) ? g_list[(size_t)b * N + rt * 128 + tid] : -1;
    __syncthreads();

    const float* base = g_xp + (size_t)b * N * L;
    int j0 = ct * 128;

    int tx = tid & 15, ty = tid >> 4;
    int lr = tid >> 1;
    int lh = (tid & 1) * 4;

    float acc[8][8];
#pragma unroll
    for (int a = 0; a < 8; a++)
#pragma unroll
        for (int c = 0; c < 8; c++) acc[a][c] = 0.f;

    int nk = (L + 7) / 8;
    {
        float4 av = ldxp4(base, rowmap[lr], lh, N, L);
        float4 bv = ldxp4(base, j0 + lr, lh, N, L);
        As[0][lh + 0][lr] = av.x; As[0][lh + 1][lr] = av.y;
        As[0][lh + 2][lr] = av.z; As[0][lh + 3][lr] = av.w;
        Bs[0][lh + 0][lr] = bv.x; Bs[0][lh + 1][lr] = bv.y;
        Bs[0][lh + 2][lr] = bv.z; Bs[0][lh + 3][lr] = bv.w;
    }
    __syncthreads();

    int buf = 0;
    for (int kc = 0; kc < nk; kc++) {
        float4 an, bn;
        bool has = (kc + 1 < nk);
        if (has) {
            an = ldxp4(base, rowmap[lr], (kc + 1) * 8 + lh, N, L);
            bn = ldxp4(base, j0 + lr, (kc + 1) * 8 + lh, N, L);
        }
#pragma unroll
        for (int k = 0; k < 8; k++) {
            float4 ra0 = *(const float4*)&As[buf][k][ty * 8];
            float4 ra1 = *(const float4*)&As[buf][k][ty * 8 + 4];
            float4 rb0 = *(const float4*)&Bs[buf][k][tx * 8];
            float4 rb1 = *(const float4*)&Bs[buf][k][tx * 8 + 4];
            float ra[8] = {ra0.x, ra0.y, ra0.z, ra0.w, ra1.x, ra1.y, ra1.z, ra1.w};
            float rb[8] = {rb0.x, rb0.y, rb0.z, rb0.w, rb1.x, rb1.y, rb1.z, rb1.w};
#pragma unroll
            for (int a = 0; a < 8; a++)
#pragma unroll
                for (int c = 0; c < 8; c++)
                    acc[a][c] += ra[a] * rb[c];
        }
        if (has) {
            int nb2 = buf ^ 1;
            As[nb2][lh + 0][lr] = an.x; As[nb2][lh + 1][lr] = an.y;
            As[nb2][lh + 2][lr] = an.z; As[nb2][lh + 3][lr] = an.w;
            Bs[nb2][lh + 0][lr] = bn.x; Bs[nb2][lh + 1][lr] = bn.y;
            Bs[nb2][lh + 2][lr] = bn.z; Bs[nb2][lh + 3][lr] = bn.w;
        }
        __syncthreads();
        buf ^= 1;
    }

    const float INF = 3.4e38f;
    float rm1 = INF, rm2a = INF, rm2 = INF, rmx = -INF;
    int ridx = 0x7fffffff;
#pragma unroll
    for (int a = 0; a < 8; a++) {
        int lrow = ty * 8 + a;
        float m1 = INF; int idx = 0x7fffffff;
#pragma unroll
        for (int c = 0; c < 8; c++) {
            int col = j0 + tx * 8 + c;
            float v = acc[a][c];
            if (col < N && v < m1) { m1 = v; idx = col; }
        }
        sred[lrow][tx] = m1; sredi[lrow][tx] = idx;
    }
    __syncthreads();
    if (tid < 128) {
#pragma unroll
        for (int q = 0; q < 16; q++) {
            float v = sred[tid][q]; int ix = sredi[tid][q];
            if (v < rm1) { rm2a = rm1; rm1 = v; ridx = ix; }
            else if (v == rm1) { rm2a = v; ridx = min(ridx, ix); }
            else if (v < rm2a) rm2a = v;
        }
    }
    __syncthreads();
#pragma unroll
    for (int a = 0; a < 8; a++) {
        int lrow = ty * 8 + a;
        float m1 = INF, m2 = INF;
#pragma unroll
        for (int c = 0; c < 8; c++) {
            int col = j0 + tx * 8 + c;
            float v = acc[a][c];
            if (col < N) {
                if (v < m1) { m2 = m1; m1 = v; }
                else if (v < m2) m2 = v;
            }
        }
        sred[lrow][tx] = m2;
    }
    __syncthreads();
    if (tid < 128) {
        rm2 = rm2a;
#pragma unroll
        for (int q = 0; q < 16; q++) rm2 = fminf(rm2, sred[tid][q]);
    }
    __syncthreads();
#pragma unroll
    for (int a = 0; a < 8; a++) {
        int lrow = ty * 8 + a;
        float mx = -INF;
#pragma unroll
        for (int c = 0; c < 8; c++) {
            int col = j0 + tx * 8 + c;
            float v = acc[a][c];
            if (col < N) mx = fmaxf(mx, v);
        }
        sred[lrow][tx] = mx;
    }
    __syncthreads();
    if (tid < 128) {
        rmx = -INF;
#pragma unroll
        for (int q = 0; q < 16; q++) rmx = fmaxf(rmx, sred[tid][q]);
        int grow = rowmap[tid];
        if (grow >= 0) {
            size_t o = (size_t)((size_t)b * N + grow) * MAX_NB + ct;
            g_pmin[o] = rm1; g_pmin2[o] = rm2; g_pmax[o] = rmx; g_pidx[o] = ridx;
        }
    }
}

// ---------- Kernel 5: merge exact strips for refined rows -----------------------
__global__ void merge2_kernel(int BN, int N, int nb, int K) {
    int n = blockIdx.x * 256 + threadIdx.x;
    if (n >= BN) return;
    if (g_flags[n] != 1) return;
    const float INF = 3.4e38f;
    float m1 = INF, m2 = INF, mx = -INF;
    int idx = 0x7fffffff;
    size_t base = (size_t)n * MAX_NB;
    for (int s = 0; s < nb; s++) {
        float pm1 = g_pmin[base + s];
        float pm2 = g_pmin2[base + s];
        float px  = g_pmax[base + s];
        int   pi  = g_pidx[base + s];
        mx = fmaxf(mx, px);
        if (pm1 < m1) { m2 = fminf(m1, pm2); m1 = pm1; idx = pi; }
        else if (pm1 == m1) { m2 = m1; idx = min(idx, pi); }
        else { m2 = fminf(m2, pm1); }
    }
    bool ok = (m1 < 0.f)
           && (-m1 > (mx + 256.f) * 1e-19f)
           && (m2 - m1 > 1e-3f)
           && (N > K + 1);
    g_flags[n]  = ok ? 0 : 2;
    g_argmin[n] = idx;
}

// ---------- Kernel 6: one-hot attention fill + h gather (write-only) ------------
__global__ void fill_kernel(float* __restrict__ h_out,
                            float* __restrict__ attn,
                            int N, int L) {
    int n = blockIdx.x;
    if (g_flags[n]) return;
    int b = n / N;
    int idx = g_argmin[n];
    int t = threadIdx.x;
    float* row = attn + (size_t)n * N;

    for (int m = t * 4; m < N; m += 256 * 4) {
        float4 v = make_float4(0.f, 0.f, 0.f, 0.f);
        if (idx >= m && idx < m + 4) {
            if (idx == m)     v.x = 1.f;
            if (idx == m + 1) v.y = 1.f;
            if (idx == m + 2) v.z = 1.f;
            if (idx == m + 3) v.w = 1.f;
        }
        if (m + 3 < N) *(float4*)(row + m) = v;
        else for (int q = 0; q < 4 && m + q < N; q++) row[m + q] = (&v.x)[q];
    }
    if (t < L) {
        const float* xpb = g_xp + (size_t)b * N * L;
        h_out[(size_t)n * L + t] = xpb[(size_t)idx * L + t];
    }
}

// ---------- Kernel 7: general fallback (flag==2; exact fp32 recompute) ----------
__global__ void attn_slow_kernel(float* __restrict__ h_out,
                                 float* __restrict__ attn,
                                 int N, int L) {
    int n = blockIdx.x;
    if (g_flags[n] != 2) return;

    extern __shared__ unsigned su[];
    float* sf = (float*)su;
    __shared__ __align__(16) float xq[MAX_L];
    __shared__ float redf[256];
    __shared__ int   warp_tot[8];
    __shared__ int   s_cnt;
    __shared__ int   s_nnz;
    __shared__ int   ilist[1024];
    const int K = 100;

    int b = n / N;
    int diag = n - b * N;
    int t = threadIdx.x;
    int lane = t & 31, w = t >> 5;
    float* row = attn + (size_t)n * N;
    const float* xpb = g_xp + (size_t)b * N * L;

    for (int l = t; l < L; l += 256) xq[l] = xpb[(size_t)diag * L + l];
    __syncthreads();
    for (int m = t; m < N; m += 256) {
        const float* xm = xpb + (size_t)m * L;
        float d = 0.f;
        for (int l = 0; l < L; l++) d += xq[l] * xm[l];
        su[m] = f2key(d);
    }
    __syncthreads();

    unsigned res = 0u;
    for (int bit = 31; bit >= 0; --bit) {
        unsigned cand = res | (1u << bit);
        if (t == 0) s_cnt = 0;
        __syncthreads();
        int c = 0;
        for (int m = t; m < N; m += 256) c += (su[m] >= cand) ? 1 : 0;
#pragma unroll
        for (int o = 16; o; o >>= 1) c += __shfl_down_sync(0xffffffffu, c, o);
        if (lane == 0) atomicAdd(&s_cnt, c);
        __syncthreads();
        if (s_cnt >= K) res = cand;
        __syncthreads();
    }

    if (t == 0) s_cnt = 0;
    __syncthreads();
    {
        int c = 0;
        for (int m = t; m < N; m += 256) c += (su[m] > res) ? 1 : 0;
#pragma unroll
        for (int o = 16; o; o >>= 1) c += __shfl_down_sync(0xffffffffu, c, o);
        if (lane == 0) atomicAdd(&s_cnt, c);
    }
    __syncthreads();
    int need = K - s_cnt;
    __syncthreads();

    int running = 0;
    float vmax = -3.4e38f;
    for (int m0 = 0; m0 < N; m0 += 256) {
        int m = m0 + t;
        bool valid = (m < N);
        unsigned u = valid ? su[m] : 0u;
        bool eq = valid && (u == res);
        unsigned ball = __ballot_sync(0xffffffffu, eq);
        if (lane == 0) warp_tot[w] = __popc(ball);
        __syncthreads();
        int woff = 0, ctot = 0;
#pragma unroll
        for (int i = 0; i < 8; i++) {
            int wt = warp_tot[i];
            ctot += wt;
            if (i < w) woff += wt;
        }
        int rank = running + woff + __popc(ball & ((1u << lane) - 1u));
        if (valid) {
            bool nb2 = (u > res) || (eq && rank < need) || (m == diag);
            float s = key2f(u);
            float v = nb2 ? s : (-1e19f * s);
            sf[m] = v;
            vmax = fmaxf(vmax, v);
        }
        running += ctot;
        __syncthreads();
    }

    redf[t] = vmax; __syncthreads();
#pragma unroll
    for (int st = 128; st; st >>= 1) { if (t < st) redf[t] = fmaxf(redf[t], redf[t + st]); __syncthreads(); }
    float M = redf[0]; __syncthreads();

    float lsum = 0.f;
    for (int m = t; m < N; m += 256) {
        float e = expf(sf[m] - M);
        sf[m] = e;
        lsum += e;
    }
    __syncthreads();
    redf[t] = lsum; __syncthreads();
#pragma unroll
    for (int st = 128; st; st >>= 1) { if (t < st) redf[t] += redf[t + st]; __syncthreads(); }
    float inv = 1.0f / redf[0]; __syncthreads();

    if (t == 0) s_nnz = 0;
    __syncthreads();
    for (int m = t; m < N; m += 256) {
        float a = sf[m] * inv;
        sf[m] = a;
        row[m] = a;
        if (a != 0.f) {
            int p = atomicAdd(&s_nnz, 1);
            if (p < 1024) ilist[p] = m;
        }
    }
    __syncthreads();
    int nnz = s_nnz;

    if (t < L) {
        float acc = 0.f;
        if (nnz == 1) {
            int m = ilist[0];
            acc = sf[m] * xpb[(size_t)m * L + t];
        } else {
            for (int m = 0; m < N; m++) {
                float a = sf[m];
                if (a != 0.f) acc += a * xpb[(size_t)m * L + t];
            }
        }
        h_out[(size_t)n * L + t] = acc;
    }
}

// ---------- launch ----------
extern "C" void kernel_launch(void* const* d_in, const int* in_sizes, int n_in,
                              void* d_out, int out_size) {
    const float* x = (const float*)d_in[0];
    const float* W = (const float*)d_in[1];

    int L = (int)(sqrt((double)in_sizes[1]) + 0.5);
    long long BN = in_sizes[0] / L;
    long long N  = (long long)out_size / BN - L;
    int Ni = (int)N;
    int B  = (int)(BN / N);
    int BNi = (int)BN;
    int nkc = (L + 31) / 32;    // K-chunks of 32 halves

    float* h_out = (float*)d_out;
    float* attn  = h_out + (size_t)BN * L;

    init_kernel<<<1, 64>>>();

    proj_kernel<<<(BNi + PROJ_ROWS - 1) / PROJ_ROWS, 256>>>(x, W, BNi, L);

    int nb = (Ni + 127) / 128;
    int tri = nb * (nb + 1) / 2;
    dim3 g2(tri, B);
    score_h2_kernel<<<g2, 256>>>(Ni, L, nb, nkc);

    merge1_kernel<<<(BNi + 255) / 256, 256>>>(BNi, Ni, nb, 100);

    dim3 g4(nb, nb, B);
    refine_kernel<<<g4, 256>>>(Ni, L, nb);

    merge2_kernel<<<(BNi + 255) / 256, 256>>>(BNi, Ni, nb, 100);

    fill_kernel<<<BNi, 256>>>(h_out, attn, Ni, L);

    size_t smem = (size_t)Ni * sizeof(float);
    attn_slow_kernel<<<BNi, 256, smem>>>(h_out, attn, Ni, L);
}

// round 10
// speedup vs baseline: 2.8900x; 1.0246x over previous
#include <cuda_runtime.h>
#include <cuda_fp16.h>
#include <math.h>
#include <cstdint>

#define MAX_BN 8192
#define MAX_L  256
#define MAX_NB 64
#define XPH_STRIDE 256   // halves per row (zero-padded)

__device__ float  g_xp [MAX_BN * MAX_L];        // fp32 projection
__device__ __half g_xph[MAX_BN * XPH_STRIDE];   // fp16 copy, zero-padded
__device__ int    g_flags[MAX_BN];
__device__ int    g_argmin[MAX_BN];
// transposed stats: [strip][global row] for coalesced access
__device__ float  g_pmin [MAX_NB * MAX_BN];
__device__ float  g_pmin2[MAX_NB * MAX_BN];
__device__ float  g_pmax [MAX_NB * MAX_BN];
__device__ int    g_pidx [MAX_NB * MAX_BN];
__device__ int    g_list[MAX_BN];
__device__ int    g_cnt[64];

#define PSTAT(s, n) ((size_t)(s) * MAX_BN + (size_t)(n))

// ---------- helpers ----------
__device__ __forceinline__ unsigned f2key(float f) {
    unsigned u = __float_as_uint(f);
    return (u & 0x80000000u) ? ~u : (u | 0x80000000u);
}
__device__ __forceinline__ float key2f(unsigned k) {
    unsigned u = (k & 0x80000000u) ? (k & 0x7fffffffu) : ~k;
    return __uint_as_float(u);
}

__global__ void init_kernel() {
    if (threadIdx.x < 64) g_cnt[threadIdx.x] = 0;
}

// ---------- Kernel 1: x_proj = x @ W^T (fp32 + fp16 copies) ----------
#define PROJ_ROWS 8
__global__ void proj_kernel(const float* __restrict__ x,
                            const float* __restrict__ W,
                            int BN, int L) {
    __shared__ float xs[PROJ_ROWS * 256];
    __shared__ float Ws[32][257];
    int n0 = blockIdx.x * PROJ_ROWS;
    int rows = min(PROJ_ROWS, BN - n0);
    int t = threadIdx.x;
    for (int i = t; i < rows * L; i += 256) xs[i] = x[(size_t)n0 * L + i];

    float acc[PROJ_ROWS];
#pragma unroll
    for (int r = 0; r < PROJ_ROWS; r++) acc[r] = 0.f;

    for (int l0 = 0; l0 < L; l0 += 32) {
        int lw = min(32, L - l0);
        __syncthreads();
        for (int idx = t; idx < L * lw; idx += 256) {
            int o = idx / lw, l = idx - o * lw;
            Ws[l][o] = W[(size_t)o * L + l0 + l];
        }
        __syncthreads();
        if (t < L) {
            for (int l = 0; l < lw; l++) {
                float w = Ws[l][t];
#pragma unroll
                for (int r = 0; r < PROJ_ROWS; r++)
                    acc[r] += xs[r * L + l0 + l] * w;
            }
        }
    }
    for (int r = 0; r < rows; r++) {
        if (t < L) {
            g_xp[(size_t)(n0 + r) * L + t] = acc[r];
            g_xph[(size_t)(n0 + r) * XPH_STRIDE + t] = __float2half_rn(acc[r]);
        } else {
            g_xph[(size_t)(n0 + r) * XPH_STRIDE + t] = __float2half_rn(0.f);
        }
    }
}

// ---------- Kernel 2: HFMA2 score GEMM (512 thr, 8x4/thread) + strip stats ------
// tid = ty*32+tx; ty 0..15 (8-row group), tx 0..31 (4-col group). Tile 128x128.
// K chunks of 32 halves (16 half2 steps), half2 accs folded to fp32 per chunk.
#define AS2(buf,kp,row) (((__half2*)pool)[((buf)*16 + (kp))*136 + (row)])
#define BS2(buf,kp,row) (((__half2*)pool)[4352 + ((buf)*16 + (kp))*136 + (row)])
#define SRED(r,q)  (((float*)pool)[(r)*33 + (q)])
#define SREDI(r,q) (((int*)(pool + 16896))[(r)*33 + (q)])

__global__ __launch_bounds__(512, 1)
void score_h2_kernel(int N, int L, int nb, int nkc) {
    __shared__ __align__(16) char pool[34816];

    int b = blockIdx.y;
    const __half* xph = g_xph + (size_t)b * N * XPH_STRIDE;

    // triangular block mapping (bj >= bi)
    int t = blockIdx.x;
    int bi;
    {
        float fnb = (float)(2 * nb + 1);
        int est = (int)((fnb - sqrtf(fnb * fnb - 8.0f * (float)t)) * 0.5f);
        if (est < 0) est = 0;
        if (est >= nb) est = nb - 1;
        bi = est;
        while (bi > 0 && (bi * nb - bi * (bi - 1) / 2) > t) bi--;
        while (((bi + 1) * nb - (bi + 1) * bi / 2) <= t) bi++;
    }
    int bj = bi + (t - (bi * nb - bi * (bi - 1) / 2));
    int i0 = bi * 128, j0 = bj * 128;

    int tid = threadIdx.x;
    int tx = tid & 31, ty = tid >> 5;
    int lr = tid >> 2;          // 0..127 row for fills
    int lq = tid & 3;           // uint4 index within 64B chunk-row

    const __half2 HZ = __float2half2_rn(0.f);
    float   acc [8][4];
    __half2 acc2[8][4];
#pragma unroll
    for (int a = 0; a < 8; a++)
#pragma unroll
        for (int c = 0; c < 4; c++) { acc[a][c] = 0.f; acc2[a][c] = HZ; }

    const uint4 Z4 = make_uint4(0u, 0u, 0u, 0u);
    auto ldrow = [&](int grow, int kc) -> uint4 {
        if (grow < N) {
            const uint4* p = (const uint4*)(xph + (size_t)grow * XPH_STRIDE);
            return p[kc * 4 + lq];
        }
        return Z4;
    };
    auto stA = [&](int buf, uint4 v) {
        AS2(buf, lq * 4 + 0, lr) = *(__half2*)&v.x;
        AS2(buf, lq * 4 + 1, lr) = *(__half2*)&v.y;
        AS2(buf, lq * 4 + 2, lr) = *(__half2*)&v.z;
        AS2(buf, lq * 4 + 3, lr) = *(__half2*)&v.w;
    };
    auto stB = [&](int buf, uint4 v) {
        BS2(buf, lq * 4 + 0, lr) = *(__half2*)&v.x;
        BS2(buf, lq * 4 + 1, lr) = *(__half2*)&v.y;
        BS2(buf, lq * 4 + 2, lr) = *(__half2*)&v.z;
        BS2(buf, lq * 4 + 3, lr) = *(__half2*)&v.w;
    };

    stA(0, ldrow(i0 + lr, 0));
    stB(0, ldrow(j0 + lr, 0));
    __syncthreads();

    int buf = 0;
    for (int kc = 0; kc < nkc; kc++) {
        uint4 a0, b0;
        bool has = (kc + 1 < nkc);
        if (has) {
            a0 = ldrow(i0 + lr, kc + 1);
            b0 = ldrow(j0 + lr, kc + 1);
        }
#pragma unroll
        for (int kp = 0; kp < 16; kp++) {
            __half2 ha[8], hb[4];
            *(uint4*)&ha[0] = *(const uint4*)&AS2(buf, kp, ty * 8);
            *(uint4*)&ha[4] = *(const uint4*)&AS2(buf, kp, ty * 8 + 4);
            *(uint4*)&hb[0] = *(const uint4*)&BS2(buf, kp, tx * 4);
#pragma unroll
            for (int a = 0; a < 8; a++)
#pragma unroll
                for (int c = 0; c < 4; c++)
                    acc2[a][c] = __hfma2(ha[a], hb[c], acc2[a][c]);
        }
#pragma unroll
        for (int a = 0; a < 8; a++)
#pragma unroll
            for (int c = 0; c < 4; c++) {
                float2 f = __half22float2(acc2[a][c]);
                acc[a][c] += f.x + f.y;
                acc2[a][c] = HZ;
            }
        if (has) { stA(buf ^ 1, a0); stB(buf ^ 1, b0); }
        __syncthreads();
        buf ^= 1;
    }

    const float INF = 3.4e38f;

    // ===== Phase A: stats per i-row (lrow = ty*8+a) over 128 j-cols =====
    float rm1 = INF, rm2 = INF, rmx = -INF;
    int ridx = 0x7fffffff;
#pragma unroll
    for (int a = 0; a < 8; a++) {
        int lrow = ty * 8 + a;
        float m1 = INF; int idx = 0x7fffffff;
#pragma unroll
        for (int c = 0; c < 4; c++) {
            int col = j0 + tx * 4 + c;
            float v = acc[a][c];
            if (col < N && v < m1) { m1 = v; idx = col; }
        }
        SRED(lrow, tx) = m1; SREDI(lrow, tx) = idx;
    }
    __syncthreads();
    float rm2a = INF;
    if (tid < 128) {
        rm1 = INF; ridx = 0x7fffffff;
#pragma unroll
        for (int q = 0; q < 32; q++) {
            float v = SRED(tid, q); int ix = SREDI(tid, q);
            if (v < rm1) { rm2a = rm1; rm1 = v; ridx = ix; }
            else if (v == rm1) { rm2a = v; ridx = min(ridx, ix); }
            else if (v < rm2a) rm2a = v;
        }
    }
    __syncthreads();
#pragma unroll
    for (int a = 0; a < 8; a++) {
        int lrow = ty * 8 + a;
        float m1 = INF, m2 = INF;
#pragma unroll
        for (int c = 0; c < 4; c++) {
            int col = j0 + tx * 4 + c;
            float v = acc[a][c];
            if (col < N) {
                if (v < m1) { m2 = m1; m1 = v; }
                else if (v < m2) m2 = v;
            }
        }
        SRED(lrow, tx) = m2;
    }
    __syncthreads();
    if (tid < 128) {
        rm2 = rm2a;
#pragma unroll
        for (int q = 0; q < 32; q++) rm2 = fminf(rm2, SRED(tid, q));
    }
    __syncthreads();
#pragma unroll
    for (int a = 0; a < 8; a++) {
        int lrow = ty * 8 + a;
        float mx = -INF;
#pragma unroll
        for (int c = 0; c < 4; c++) {
            int col = j0 + tx * 4 + c;
            float v = acc[a][c];
            if (col < N) mx = fmaxf(mx, v);
        }
        SRED(lrow, tx) = mx;
    }
    __syncthreads();
    if (tid < 128) {
        rmx = -INF;
#pragma unroll
        for (int q = 0; q < 32; q++) rmx = fmaxf(rmx, SRED(tid, q));
        if (i0 + tid < N) {
            size_t o = PSTAT(bj, (size_t)b * N + i0 + tid);
            g_pmin[o] = rm1; g_pmin2[o] = rm2; g_pmax[o] = rmx; g_pidx[o] = ridx;
        }
    }

    // ===== Phase B (mirror): stats per j-col (lcol = tx*4+c) over 128 i-rows ====
    if (bi != bj) {
        __syncthreads();
#pragma unroll
        for (int c = 0; c < 4; c++) {
            int lcol = tx * 4 + c;
            float m1 = INF; int idx = 0x7fffffff;
#pragma unroll
            for (int a = 0; a < 8; a++) {
                int grow = i0 + ty * 8 + a;
                float v = acc[a][c];
                if (grow < N && v < m1) { m1 = v; idx = grow; }
            }
            SRED(lcol, ty) = m1; SREDI(lcol, ty) = idx;
        }
        __syncthreads();
        rm2a = INF;
        if (tid < 128) {
            rm1 = INF; ridx = 0x7fffffff;
#pragma unroll
            for (int q = 0; q < 16; q++) {
                float v = SRED(tid, q); int ix = SREDI(tid, q);
                if (v < rm1) { rm2a = rm1; rm1 = v; ridx = ix; }
                else if (v == rm1) { rm2a = v; ridx = min(ridx, ix); }
                else if (v < rm2a) rm2a = v;
            }
        }
        __syncthreads();
#pragma unroll
        for (int c = 0; c < 4; c++) {
            int lcol = tx * 4 + c;
            float m1 = INF, m2 = INF;
#pragma unroll
            for (int a = 0; a < 8; a++) {
                int grow = i0 + ty * 8 + a;
                float v = acc[a][c];
                if (grow < N) {
                    if (v < m1) { m2 = m1; m1 = v; }
                    else if (v < m2) m2 = v;
                }
            }
            SRED(lcol, ty) = m2;
        }
        __syncthreads();
        if (tid < 128) {
            rm2 = rm2a;
#pragma unroll
            for (int q = 0; q < 16; q++) rm2 = fminf(rm2, SRED(tid, q));
        }
        __syncthreads();
#pragma unroll
        for (int c = 0; c < 4; c++) {
            int lcol = tx * 4 + c;
            float mx = -INF;
#pragma unroll
            for (int a = 0; a < 8; a++) {
                int grow = i0 + ty * 8 + a;
                float v = acc[a][c];
                if (grow < N) mx = fmaxf(mx, v);
            }
            SRED(lcol, ty) = mx;
        }
        __syncthreads();
        if (tid < 128) {
            rmx = -INF;
#pragma unroll
            for (int q = 0; q < 16; q++) rmx = fmaxf(rmx, SRED(tid, q));
            if (j0 + tid < N) {
                size_t o = PSTAT(bi, (size_t)b * N + j0 + tid);
                g_pmin[o] = rm1; g_pmin2[o] = rm2; g_pmax[o] = rmx; g_pidx[o] = ridx;
            }
        }
    }
}

// ---------- Kernel 3: merge approx strips -> certify or enqueue for refine -----
__global__ void merge1_kernel(int BN, int N, int nb, int K) {
    int n = blockIdx.x * 256 + threadIdx.x;
    if (n >= BN) return;
    const float INF = 3.4e38f;
    float m1 = INF, m2 = INF, mx = -INF;
    int idx = 0x7fffffff;
    for (int s = 0; s < nb; s++) {
        size_t o = PSTAT(s, n);
        float pm1 = g_pmin[o];
        float pm2 = g_pmin2[o];
        float px  = g_pmax[o];
        int   pi  = g_pidx[o];
        mx = fmaxf(mx, px);
        if (pm1 < m1) { m2 = fminf(m1, pm2); m1 = pm1; idx = pi; }
        else if (pm1 == m1) { m2 = m1; idx = min(idx, pi); }
        else { m2 = fminf(m2, pm1); }
    }
    // fp16-noise certified one-hot guard (noise sigma ~0.01-0.02)
    bool ok = (m1 < -1.0f)
           && (-m1 > (mx + 256.f) * 1e-19f)
           && (m2 - m1 > 0.25f)
           && (N > K + 1);
    if (ok) {
        g_flags[n] = 0;
        g_argmin[n] = idx;
    } else {
        g_flags[n] = 1;
        int b = n / N, r = n - b * N;
        int p = atomicAdd(&g_cnt[b], 1);
        g_list[(size_t)b * N + p] = r;
    }
}

// ---------- bounds-safe float4 load (fp32) ----------
__device__ __forceinline__ float4 ldxp4(const float* __restrict__ base,
                                        long long row, int k, int N, int L) {
    float4 v = make_float4(0.f, 0.f, 0.f, 0.f);
    if (row >= 0 && row < N) {
        const float* p = base + (size_t)row * L + k;
        if (k + 3 < L) {
            if ((((unsigned long long)(uintptr_t)p) & 15ull) == 0)
                v = *(const float4*)p;
            else { v.x = p[0]; v.y = p[1]; v.z = p[2]; v.w = p[3]; }
        } else {
            if (k     < L) v.x = p[0];
            if (k + 1 < L) v.y = p[1];
            if (k + 2 < L) v.z = p[2];
        }
    }
    return v;
}

// ---------- Kernel 4: fp32 refine GEMM over gathered flagged rows ---------------
__global__ __launch_bounds__(256, 2)
void refine_kernel(int N, int L, int nb) {
    int b  = blockIdx.z;
    int ct = blockIdx.x;
    int rt = blockIdx.y;
    int cnt = g_cnt[b];
    if (rt * 128 >= cnt) return;

    __shared__ __align__(16) float As[2][8][136];
    __shared__ __align__(16) float Bs[2][8][136];
    __shared__ float sred[128][17];
    __shared__ int   sredi[128][17];
    __shared__ int   rowmap[128];

    int tid = threadIdx.x;
    if (tid < 128)
        rowmap[tid] = (rt * 128 + tid < cnt) ? g_list[(size_t)b * N + rt * 128 + tid] : -1;
    __syncthreads();

    const float* base = g_xp + (size_t)b * N * L;
    int j0 = ct * 128;

    int tx = tid & 15, ty = tid >> 4;
    int lr = tid >> 1;
    int lh = (tid & 1) * 4;

    float acc[8][8];
#pragma unroll
    for (int a = 0; a < 8; a++)
#pragma unroll
        for (int c = 0; c < 8; c++) acc[a][c] = 0.f;

    int nk = (L + 7) / 8;
    {
        float4 av = ldxp4(base, rowmap[lr], lh, N, L);
        float4 bv = ldxp4(base, j0 + lr, lh, N, L);
        As[0][lh + 0][lr] = av.x; As[0][lh + 1][lr] = av.y;
        As[0][lh + 2][lr] = av.z; As[0][lh + 3][lr] = av.w;
        Bs[0][lh + 0][lr] = bv.x; Bs[0][lh + 1][lr] = bv.y;
        Bs[0][lh + 2][lr] = bv.z; Bs[0][lh + 3][lr] = bv.w;
    }
    __syncthreads();

    int buf = 0;
    for (int kc = 0; kc < nk; kc++) {
        float4 an, bn;
        bool has = (kc + 1 < nk);
        if (has) {
            an = ldxp4(base, rowmap[lr], (kc + 1) * 8 + lh, N, L);
            bn = ldxp4(base, j0 + lr, (kc + 1) * 8 + lh, N, L);
        }
#pragma unroll
        for (int k = 0; k < 8; k++) {
            float4 ra0 = *(const float4*)&As[buf][k][ty * 8];
            float4 ra1 = *(const float4*)&As[buf][k][ty * 8 + 4];
            float4 rb0 = *(const float4*)&Bs[buf][k][tx * 8];
            float4 rb1 = *(const float4*)&Bs[buf][k][tx * 8 + 4];
            float ra[8] = {ra0.x, ra0.y, ra0.z, ra0.w, ra1.x, ra1.y, ra1.z, ra1.w};
            float rb[8] = {rb0.x, rb0.y, rb0.z, rb0.w, rb1.x, rb1.y, rb1.z, rb1.w};
#pragma unroll
            for (int a = 0; a < 8; a++)
#pragma unroll
                for (int c = 0; c < 8; c++)
                    acc[a][c] += ra[a] * rb[c];
        }
        if (has) {
            int nb2 = buf ^ 1;
            As[nb2][lh + 0][lr] = an.x; As[nb2][lh + 1][lr] = an.y;
            As[nb2][lh + 2][lr] = an.z; As[nb2][lh + 3][lr] = an.w;
            Bs[nb2][lh + 0][lr] = bn.x; Bs[nb2][lh + 1][lr] = bn.y;
            Bs[nb2][lh + 2][lr] = bn.z; Bs[nb2][lh + 3][lr] = bn.w;
        }
        __syncthreads();
        buf ^= 1;
    }

    const float INF = 3.4e38f;
    float rm1 = INF, rm2a = INF, rm2 = INF, rmx = -INF;
    int ridx = 0x7fffffff;
#pragma unroll
    for (int a = 0; a < 8; a++) {
        int lrow = ty * 8 + a;
        float m1 = INF; int idx = 0x7fffffff;
#pragma unroll
        for (int c = 0; c < 8; c++) {
            int col = j0 + tx * 8 + c;
            float v = acc[a][c];
            if (col < N && v < m1) { m1 = v; idx = col; }
        }
        sred[lrow][tx] = m1; sredi[lrow][tx] = idx;
    }
    __syncthreads();
    if (tid < 128) {
#pragma unroll
        for (int q = 0; q < 16; q++) {
            float v = sred[tid][q]; int ix = sredi[tid][q];
            if (v < rm1) { rm2a = rm1; rm1 = v; ridx = ix; }
            else if (v == rm1) { rm2a = v; ridx = min(ridx, ix); }
            else if (v < rm2a) rm2a = v;
        }
    }
    __syncthreads();
#pragma unroll
    for (int a = 0; a < 8; a++) {
        int lrow = ty * 8 + a;
        float m1 = INF, m2 = INF;
#pragma unroll
        for (int c = 0; c < 8; c++) {
            int col = j0 + tx * 8 + c;
            float v = acc[a][c];
            if (col < N) {
                if (v < m1) { m2 = m1; m1 = v; }
                else if (v < m2) m2 = v;
            }
        }
        sred[lrow][tx] = m2;
    }
    __syncthreads();
    if (tid < 128) {
        rm2 = rm2a;
#pragma unroll
        for (int q = 0; q < 16; q++) rm2 = fminf(rm2, sred[tid][q]);
    }
    __syncthreads();
#pragma unroll
    for (int a = 0; a < 8; a++) {
        int lrow = ty * 8 + a;
        float mx = -INF;
#pragma unroll
        for (int c = 0; c < 8; c++) {
            int col = j0 + tx * 8 + c;
            float v = acc[a][c];
            if (col < N) mx = fmaxf(mx, v);
        }
        sred[lrow][tx] = mx;
    }
    __syncthreads();
    if (tid < 128) {
        rmx = -INF;
#pragma unroll
        for (int q = 0; q < 16; q++) rmx = fmaxf(rmx, sred[tid][q]);
        int grow = rowmap[tid];
        if (grow >= 0) {
            size_t o = PSTAT(ct, (size_t)b * N + grow);
            g_pmin[o] = rm1; g_pmin2[o] = rm2; g_pmax[o] = rmx; g_pidx[o] = ridx;
        }
    }
}

// ---------- Kernel 5: merge exact strips for refined rows -----------------------
__global__ void merge2_kernel(int BN, int N, int nb, int K) {
    int n = blockIdx.x * 256 + threadIdx.x;
    if (n >= BN) return;
    if (g_flags[n] != 1) return;
    const float INF = 3.4e38f;
    float m1 = INF, m2 = INF, mx = -INF;
    int idx = 0x7fffffff;
    for (int s = 0; s < nb; s++) {
        size_t o = PSTAT(s, n);
        float pm1 = g_pmin[o];
        float pm2 = g_pmin2[o];
        float px  = g_pmax[o];
        int   pi  = g_pidx[o];
        mx = fmaxf(mx, px);
        if (pm1 < m1) { m2 = fminf(m1, pm2); m1 = pm1; idx = pi; }
        else if (pm1 == m1) { m2 = m1; idx = min(idx, pi); }
        else { m2 = fminf(m2, pm1); }
    }
    bool ok = (m1 < 0.f)
           && (-m1 > (mx + 256.f) * 1e-19f)
           && (m2 - m1 > 1e-3f)
           && (N > K + 1);
    g_flags[n]  = ok ? 0 : 2;
    g_argmin[n] = idx;
}

// ---------- Kernel 6: one-hot attention fill + h gather (write-only) ------------
__global__ void fill_kernel(float* __restrict__ h_out,
                            float* __restrict__ attn,
                            int N, int L) {
    int n = blockIdx.x;
    if (g_flags[n]) return;
    int b = n / N;
    int idx = g_argmin[n];
    int t = threadIdx.x;
    float* row = attn + (size_t)n * N;

    for (int m = t * 4; m < N; m += 256 * 4) {
        float4 v = make_float4(0.f, 0.f, 0.f, 0.f);
        if (idx >= m && idx < m + 4) {
            if (idx == m)     v.x = 1.f;
            if (idx == m + 1) v.y = 1.f;
            if (idx == m + 2) v.z = 1.f;
            if (idx == m + 3) v.w = 1.f;
        }
        if (m + 3 < N) *(float4*)(row + m) = v;
        else for (int q = 0; q < 4 && m + q < N; q++) row[m + q] = (&v.x)[q];
    }
    if (t < L) {
        const float* xpb = g_xp + (size_t)b * N * L;
        h_out[(size_t)n * L + t] = xpb[(size_t)idx * L + t];
    }
}

// ---------- Kernel 7: general fallback (flag==2; exact fp32 recompute) ----------
__global__ void attn_slow_kernel(float* __restrict__ h_out,
                                 float* __restrict__ attn,
                                 int N, int L) {
    int n = blockIdx.x;
    if (g_flags[n] != 2) return;

    extern __shared__ unsigned su[];
    float* sf = (float*)su;
    __shared__ __align__(16) float xq[MAX_L];
    __shared__ float redf[256];
    __shared__ int   warp_tot[8];
    __shared__ int   s_cnt;
    __shared__ int   s_nnz;
    __shared__ int   ilist[1024];
    const int K = 100;

    int b = n / N;
    int diag = n - b * N;
    int t = threadIdx.x;
    int lane = t & 31, w = t >> 5;
    float* row = attn + (size_t)n * N;
    const float* xpb = g_xp + (size_t)b * N * L;

    for (int l = t; l < L; l += 256) xq[l] = xpb[(size_t)diag * L + l];
    __syncthreads();
    for (int m = t; m < N; m += 256) {
        const float* xm = xpb + (size_t)m * L;
        float d = 0.f;
        for (int l = 0; l < L; l++) d += xq[l] * xm[l];
        su[m] = f2key(d);
    }
    __syncthreads();

    unsigned res = 0u;
    for (int bit = 31; bit >= 0; --bit) {
        unsigned cand = res | (1u << bit);
        if (t == 0) s_cnt = 0;
        __syncthreads();
        int c = 0;
        for (int m = t; m < N; m += 256) c += (su[m] >= cand) ? 1 : 0;
#pragma unroll
        for (int o = 16; o; o >>= 1) c += __shfl_down_sync(0xffffffffu, c, o);
        if (lane == 0) atomicAdd(&s_cnt, c);
        __syncthreads();
        if (s_cnt >= K) res = cand;
        __syncthreads();
    }

    if (t == 0) s_cnt = 0;
    __syncthreads();
    {
        int c = 0;
        for (int m = t; m < N; m += 256) c += (su[m] > res) ? 1 : 0;
#pragma unroll
        for (int o = 16; o; o >>= 1) c += __shfl_down_sync(0xffffffffu, c, o);
        if (lane == 0) atomicAdd(&s_cnt, c);
    }
    __syncthreads();
    int need = K - s_cnt;
    __syncthreads();

    int running = 0;
    float vmax = -3.4e38f;
    for (int m0 = 0; m0 < N; m0 += 256) {
        int m = m0 + t;
        bool valid = (m < N);
        unsigned u = valid ? su[m] : 0u;
        bool eq = valid && (u == res);
        unsigned ball = __ballot_sync(0xffffffffu, eq);
        if (lane == 0) warp_tot[w] = __popc(ball);
        __syncthreads();
        int woff = 0, ctot = 0;
#pragma unroll
        for (int i = 0; i < 8; i++) {
            int wt = warp_tot[i];
            ctot += wt;
            if (i < w) woff += wt;
        }
        int rank = running + woff + __popc(ball & ((1u << lane) - 1u));
        if (valid) {
            bool nb2 = (u > res) || (eq && rank < need) || (m == diag);
            float s = key2f(u);
            float v = nb2 ? s : (-1e19f * s);
            sf[m] = v;
            vmax = fmaxf(vmax, v);
        }
        running += ctot;
        __syncthreads();
    }

    redf[t] = vmax; __syncthreads();
#pragma unroll
    for (int st = 128; st; st >>= 1) { if (t < st) redf[t] = fmaxf(redf[t], redf[t + st]); __syncthreads(); }
    float M = redf[0]; __syncthreads();

    float lsum = 0.f;
    for (int m = t; m < N; m += 256) {
        float e = expf(sf[m] - M);
        sf[m] = e;
        lsum += e;
    }
    __syncthreads();
    redf[t] = lsum; __syncthreads();
#pragma unroll
    for (int st = 128; st; st >>= 1) { if (t < st) redf[t] += redf[t + st]; __syncthreads(); }
    float inv = 1.0f / redf[0]; __syncthreads();

    if (t == 0) s_nnz = 0;
    __syncthreads();
    for (int m = t; m < N; m += 256) {
        float a = sf[m] * inv;
        sf[m] = a;
        row[m] = a;
        if (a != 0.f) {
            int p = atomicAdd(&s_nnz, 1);
            if (p < 1024) ilist[p] = m;
        }
    }
    __syncthreads();
    int nnz = s_nnz;

    if (t < L) {
        float acc = 0.f;
        if (nnz == 1) {
            int m = ilist[0];
            acc = sf[m] * xpb[(size_t)m * L + t];
        } else {
            for (int m = 0; m < N; m++) {
                float a = sf[m];
                if (a != 0.f) acc += a * xpb[(size_t)m * L + t];
            }
        }
        h_out[(size_t)n * L + t] = acc;
    }
}

// ---------- launch ----------
extern "C" void kernel_launch(void* const* d_in, const int* in_sizes, int n_in,
                              void* d_out, int out_size) {
    const float* x = (const float*)d_in[0];
    const float* W = (const float*)d_in[1];

    int L = (int)(sqrt((double)in_sizes[1]) + 0.5);
    long long BN = in_sizes[0] / L;
    long long N  = (long long)out_size / BN - L;
    int Ni = (int)N;
    int B  = (int)(BN / N);
    int BNi = (int)BN;
    int nkc = (L + 31) / 32;    // K-chunks of 32 halves

    float* h_out = (float*)d_out;
    float* attn  = h_out + (size_t)BN * L;

    init_kernel<<<1, 64>>>();

    proj_kernel<<<(BNi + PROJ_ROWS - 1) / PROJ_ROWS, 256>>>(x, W, BNi, L);

    int nb = (Ni + 127) / 128;
    int tri = nb * (nb + 1) / 2;
    dim3 g2(tri, B);
    score_h2_kernel<<<g2, 512>>>(Ni, L, nb, nkc);

    merge1_kernel<<<(BNi + 255) / 256, 256>>>(BNi, Ni, nb, 100);

    dim3 g4(nb, nb, B);
    refine_kernel<<<g4, 256>>>(Ni, L, nb);

    merge2_kernel<<<(BNi + 255) / 256, 256>>>(BNi, Ni, nb, 100);

    fill_kernel<<<BNi, 256>>>(h_out, attn, Ni, L);

    size_t smem = (size_t)Ni * sizeof(float);
    attn_slow_kernel<<<BNi, 256, smem>>>(h_out, attn, Ni, L);
}

// round 11
// speedup vs baseline: 4.9327x; 1.7068x over previous
#include <cuda_runtime.h>
#include <math.h>
#include <cstdint>

#define MAX_BN 8192
#define MAX_L  256
#define MAX_NB 64

__device__ float g_xp[MAX_BN * MAX_L];
__device__ int   g_flags[MAX_BN];
__device__ int   g_argmin[MAX_BN];
// transposed stats: [strip][global row] for coalesced merge
__device__ float g_pmin [MAX_NB * MAX_BN];
__device__ float g_pmin2[MAX_NB * MAX_BN];
__device__ float g_pmax [MAX_NB * MAX_BN];
__device__ int   g_pidx [MAX_NB * MAX_BN];

#define PSTAT(s, n) ((size_t)(s) * MAX_BN + (size_t)(n))

// ---------- helpers ----------
__device__ __forceinline__ unsigned f2key(float f) {
    unsigned u = __float_as_uint(f);
    return (u & 0x80000000u) ? ~u : (u | 0x80000000u);
}
__device__ __forceinline__ float key2f(unsigned k) {
    unsigned u = (k & 0x80000000u) ? (k & 0x7fffffffu) : ~k;
    return __uint_as_float(u);
}

// ---------- Kernel 1: x_proj = x @ W^T ----------
#define PROJ_ROWS 8
__global__ void proj_kernel(const float* __restrict__ x,
                            const float* __restrict__ W,
                            int BN, int L) {
    __shared__ float xs[PROJ_ROWS * 256];
    __shared__ float Ws[32][257];
    int n0 = blockIdx.x * PROJ_ROWS;
    int rows = min(PROJ_ROWS, BN - n0);
    int t = threadIdx.x;
    for (int i = t; i < rows * L; i += 256) xs[i] = x[(size_t)n0 * L + i];

    float acc[PROJ_ROWS];
#pragma unroll
    for (int r = 0; r < PROJ_ROWS; r++) acc[r] = 0.f;

    for (int l0 = 0; l0 < L; l0 += 32) {
        int lw = min(32, L - l0);
        __syncthreads();
        for (int idx = t; idx < L * lw; idx += 256) {
            int o = idx / lw, l = idx - o * lw;
            Ws[l][o] = W[(size_t)o * L + l0 + l];
        }
        __syncthreads();
        if (t < L) {
            for (int l = 0; l < lw; l++) {
                float w = Ws[l][t];
#pragma unroll
                for (int r = 0; r < PROJ_ROWS; r++)
                    acc[r] += xs[r * L + l0 + l] * w;
            }
        }
    }
    if (t < L)
        for (int r = 0; r < rows; r++)
            g_xp[(size_t)(n0 + r) * L + t] = acc[r];
}

// ---------- bounds-safe float4 load ----------
__device__ __forceinline__ float4 ldxp4(const float* __restrict__ base,
                                        int row, int k, int N, int L) {
    float4 v = make_float4(0.f, 0.f, 0.f, 0.f);
    if (row < N) {
        const float* p = base + (size_t)row * L + k;
        if (k + 3 < L) {
            if ((((unsigned long long)(uintptr_t)p) & 15ull) == 0)
                v = *(const float4*)p;
            else { v.x = p[0]; v.y = p[1]; v.z = p[2]; v.w = p[3]; }
        } else {
            if (k     < L) v.x = p[0];
            if (k + 1 < L) v.y = p[1];
            if (k + 2 < L) v.z = p[2];
        }
    }
    return v;
}

// ---------- Kernel 2: fp32 symmetric score GEMM + strip stats (smem union) -----
// 256 thr, 128x128 tile, 8x8/thread, double-buffered. Reduction scratch overlays
// the GEMM smem buffers (union) -> 17.4 KB total -> 2 resident blocks/SM.
#define ASF(buf,k,row) (((float*)pool)[((buf)*8 + (k))*136 + (row)])
#define BSF(buf,k,row) (((float*)pool)[2176 + ((buf)*8 + (k))*136 + (row)])
#define SREDF(r,q)  (((float*)pool)[(r)*17 + (q)])
#define SREDI(r,q)  (((int*)pool)[2176 + (r)*17 + (q)])

__global__ __launch_bounds__(256, 2)
void score_stats_kernel(int N, int L, int nb) {
    __shared__ __align__(16) char pool[17408];

    int b = blockIdx.y;
    const float* base = g_xp + (size_t)b * N * L;

    // triangular block mapping (bj >= bi)
    int t = blockIdx.x;
    int bi;
    {
        float fnb = (float)(2 * nb + 1);
        int est = (int)((fnb - sqrtf(fnb * fnb - 8.0f * (float)t)) * 0.5f);
        if (est < 0) est = 0;
        if (est >= nb) est = nb - 1;
        bi = est;
        while (bi > 0 && (bi * nb - bi * (bi - 1) / 2) > t) bi--;
        while (((bi + 1) * nb - (bi + 1) * bi / 2) <= t) bi++;
    }
    int bj = bi + (t - (bi * nb - bi * (bi - 1) / 2));
    int i0 = bi * 128, j0 = bj * 128;

    int tid = threadIdx.x;
    int tx = tid & 15, ty = tid >> 4;
    int lr = tid >> 1;
    int lh = (tid & 1) * 4;

    float acc[8][8];
#pragma unroll
    for (int a = 0; a < 8; a++)
#pragma unroll
        for (int c = 0; c < 8; c++) acc[a][c] = 0.f;

    int nk = (L + 7) / 8;

    {
        float4 av = ldxp4(base, i0 + lr, lh, N, L);
        float4 bv = ldxp4(base, j0 + lr, lh, N, L);
        ASF(0, lh + 0, lr) = av.x; ASF(0, lh + 1, lr) = av.y;
        ASF(0, lh + 2, lr) = av.z; ASF(0, lh + 3, lr) = av.w;
        BSF(0, lh + 0, lr) = bv.x; BSF(0, lh + 1, lr) = bv.y;
        BSF(0, lh + 2, lr) = bv.z; BSF(0, lh + 3, lr) = bv.w;
    }
    __syncthreads();

    int buf = 0;
    for (int kc = 0; kc < nk; kc++) {
        float4 an, bn;
        bool has = (kc + 1 < nk);
        if (has) {
            an = ldxp4(base, i0 + lr, (kc + 1) * 8 + lh, N, L);
            bn = ldxp4(base, j0 + lr, (kc + 1) * 8 + lh, N, L);
        }
#pragma unroll
        for (int k = 0; k < 8; k++) {
            float4 ra0 = *(const float4*)&ASF(buf, k, ty * 8);
            float4 ra1 = *(const float4*)&ASF(buf, k, ty * 8 + 4);
            float4 rb0 = *(const float4*)&BSF(buf, k, tx * 8);
            float4 rb1 = *(const float4*)&BSF(buf, k, tx * 8 + 4);
            float ra[8] = {ra0.x, ra0.y, ra0.z, ra0.w, ra1.x, ra1.y, ra1.z, ra1.w};
            float rb[8] = {rb0.x, rb0.y, rb0.z, rb0.w, rb1.x, rb1.y, rb1.z, rb1.w};
#pragma unroll
            for (int a = 0; a < 8; a++)
#pragma unroll
                for (int c = 0; c < 8; c++)
                    acc[a][c] += ra[a] * rb[c];
        }
        if (has) {
            int nb2 = buf ^ 1;
            ASF(nb2, lh + 0, lr) = an.x; ASF(nb2, lh + 1, lr) = an.y;
            ASF(nb2, lh + 2, lr) = an.z; ASF(nb2, lh + 3, lr) = an.w;
            BSF(nb2, lh + 0, lr) = bn.x; BSF(nb2, lh + 1, lr) = bn.y;
            BSF(nb2, lh + 2, lr) = bn.z; BSF(nb2, lh + 3, lr) = bn.w;
        }
        __syncthreads();
        buf ^= 1;
    }
    // GEMM done; pool is now free for reduction scratch (all reads completed).

    const float INF = 3.4e38f;
    float rm1 = INF, rm2 = INF, rm2a = INF, rmx = -INF;
    int ridx = 0x7fffffff;

    // ===== Phase A: stats per i-row over 128 j-cols (3 passes) =====
#pragma unroll
    for (int a = 0; a < 8; a++) {
        int lrow = ty * 8 + a;
        float m1 = INF; int idx = 0x7fffffff;
#pragma unroll
        for (int c = 0; c < 8; c++) {
            int col = j0 + tx * 8 + c;
            float v = acc[a][c];
            if (col < N && v < m1) { m1 = v; idx = col; }
        }
        SREDF(lrow, tx) = m1; SREDI(lrow, tx) = idx;
    }
    __syncthreads();
    if (tid < 128) {
        rm1 = INF; rm2a = INF; ridx = 0x7fffffff;
#pragma unroll
        for (int q = 0; q < 16; q++) {
            float v = SREDF(tid, q); int ix = SREDI(tid, q);
            if (v < rm1) { rm2a = rm1; rm1 = v; ridx = ix; }
            else if (v == rm1) { rm2a = v; ridx = min(ridx, ix); }
            else if (v < rm2a) rm2a = v;
        }
    }
    __syncthreads();
#pragma unroll
    for (int a = 0; a < 8; a++) {
        int lrow = ty * 8 + a;
        float m1 = INF, m2 = INF;
#pragma unroll
        for (int c = 0; c < 8; c++) {
            int col = j0 + tx * 8 + c;
            float v = acc[a][c];
            if (col < N) {
                if (v < m1) { m2 = m1; m1 = v; }
                else if (v < m2) m2 = v;
            }
        }
        SREDF(lrow, tx) = m2;
    }
    __syncthreads();
    if (tid < 128) {
        rm2 = rm2a;
#pragma unroll
        for (int q = 0; q < 16; q++) rm2 = fminf(rm2, SREDF(tid, q));
    }
    __syncthreads();
#pragma unroll
    for (int a = 0; a < 8; a++) {
        int lrow = ty * 8 + a;
        float mx = -INF;
#pragma unroll
        for (int c = 0; c < 8; c++) {
            int col = j0 + tx * 8 + c;
            float v = acc[a][c];
            if (col < N) mx = fmaxf(mx, v);
        }
        SREDF(lrow, tx) = mx;
    }
    __syncthreads();
    if (tid < 128) {
        rmx = -INF;
#pragma unroll
        for (int q = 0; q < 16; q++) rmx = fmaxf(rmx, SREDF(tid, q));
        if (i0 + tid < N) {
            size_t o = PSTAT(bj, (size_t)b * N + i0 + tid);
            g_pmin[o] = rm1; g_pmin2[o] = rm2; g_pmax[o] = rmx; g_pidx[o] = ridx;
        }
    }

    // ===== Phase B (mirror): stats per j-col over 128 i-rows =====
    if (bi != bj) {
        __syncthreads();
#pragma unroll
        for (int c = 0; c < 8; c++) {
            int lcol = tx * 8 + c;
            float m1 = INF; int idx = 0x7fffffff;
#pragma unroll
            for (int a = 0; a < 8; a++) {
                int grow = i0 + ty * 8 + a;
                float v = acc[a][c];
                if (grow < N && v < m1) { m1 = v; idx = grow; }
            }
            SREDF(lcol, ty) = m1; SREDI(lcol, ty) = idx;
        }
        __syncthreads();
        if (tid < 128) {
            rm1 = INF; rm2a = INF; ridx = 0x7fffffff;
#pragma unroll
            for (int q = 0; q < 16; q++) {
                float v = SREDF(tid, q); int ix = SREDI(tid, q);
                if (v < rm1) { rm2a = rm1; rm1 = v; ridx = ix; }
                else if (v == rm1) { rm2a = v; ridx = min(ridx, ix); }
                else if (v < rm2a) rm2a = v;
            }
        }
        __syncthreads();
#pragma unroll
        for (int c = 0; c < 8; c++) {
            int lcol = tx * 8 + c;
            float m1 = INF, m2 = INF;
#pragma unroll
            for (int a = 0; a < 8; a++) {
                int grow = i0 + ty * 8 + a;
                float v = acc[a][c];
                if (grow < N) {
                    if (v < m1) { m2 = m1; m1 = v; }
                    else if (v < m2) m2 = v;
                }
            }
            SREDF(lcol, ty) = m2;
        }
        __syncthreads();
        if (tid < 128) {
            rm2 = rm2a;
#pragma unroll
            for (int q = 0; q < 16; q++) rm2 = fminf(rm2, SREDF(tid, q));
        }
        __syncthreads();
#pragma unroll
        for (int c = 0; c < 8; c++) {
            int lcol = tx * 8 + c;
            float mx = -INF;
#pragma unroll
            for (int a = 0; a < 8; a++) {
                int grow = i0 + ty * 8 + a;
                float v = acc[a][c];
                if (grow < N) mx = fmaxf(mx, v);
            }
            SREDF(lcol, ty) = mx;
        }
        __syncthreads();
        if (tid < 128) {
            rmx = -INF;
#pragma unroll
            for (int q = 0; q < 16; q++) rmx = fmaxf(rmx, SREDF(tid, q));
            if (j0 + tid < N) {
                size_t o = PSTAT(bi, (size_t)b * N + j0 + tid);
                g_pmin[o] = rm1; g_pmin2[o] = rm2; g_pmax[o] = rmx; g_pidx[o] = ridx;
            }
        }
    }
}

// ---------- Kernel 3: merge strips (coalesced) -> argmin + guard flag ----------
__global__ void merge_kernel(int BN, int N, int nb, int K) {
    int n = blockIdx.x * 256 + threadIdx.x;
    if (n >= BN) return;
    const float INF = 3.4e38f;
    float m1 = INF, m2 = INF, mx = -INF;
    int idx = 0x7fffffff;
    for (int s = 0; s < nb; s++) {
        size_t o = PSTAT(s, n);
        float pm1 = g_pmin[o];
        float pm2 = g_pmin2[o];
        float px  = g_pmax[o];
        int   pi  = g_pidx[o];
        mx = fmaxf(mx, px);
        if (pm1 < m1) { m2 = fminf(m1, pm2); m1 = pm1; idx = pi; }
        else if (pm1 == m1) { m2 = m1; idx = min(idx, pi); }
        else { m2 = fminf(m2, pm1); }
    }
    // exact fp32 one-hot guards (unique argmin + exp-underflow margins)
    bool ok = (m1 < 0.f)
           && (-m1 > (mx + 256.f) * 1e-19f)
           && (m2 - m1 > 1e-4f)
           && (N > K + 1);
    g_flags[n]  = ok ? 0 : 1;
    g_argmin[n] = idx;
}

// ---------- Kernel 4: one-hot attention fill + h gather (write-only) ------------
__global__ void fill_kernel(float* __restrict__ h_out,
                            float* __restrict__ attn,
                            int N, int L) {
    int n = blockIdx.x;
    if (g_flags[n]) return;
    int b = n / N;
    int idx = g_argmin[n];
    int t = threadIdx.x;
    float* row = attn + (size_t)n * N;

    for (int m = t * 4; m < N; m += 256 * 4) {
        float4 v = make_float4(0.f, 0.f, 0.f, 0.f);
        if (idx >= m && idx < m + 4) {
            if (idx == m)     v.x = 1.f;
            if (idx == m + 1) v.y = 1.f;
            if (idx == m + 2) v.z = 1.f;
            if (idx == m + 3) v.w = 1.f;
        }
        if (m + 3 < N) *(float4*)(row + m) = v;
        else for (int q = 0; q < 4 && m + q < N; q++) row[m + q] = (&v.x)[q];
    }
    if (t < L) {
        const float* xpb = g_xp + (size_t)b * N * L;
        h_out[(size_t)n * L + t] = xpb[(size_t)idx * L + t];
    }
}

// ---------- Kernel 5: general fallback (flag-gated; exact fp32 recompute) -------
__global__ void attn_slow_kernel(float* __restrict__ h_out,
                                 float* __restrict__ attn,
                                 int N, int L) {
    int n = blockIdx.x;
    if (g_flags[n] == 0) return;

    extern __shared__ unsigned su[];
    float* sf = (float*)su;
    __shared__ __align__(16) float xq[MAX_L];
    __shared__ float redf[256];
    __shared__ int   warp_tot[8];
    __shared__ int   s_cnt;
    __shared__ int   s_nnz;
    __shared__ int   ilist[1024];
    const int K = 100;

    int b = n / N;
    int diag = n - b * N;
    int t = threadIdx.x;
    int lane = t & 31, w = t >> 5;
    float* row = attn + (size_t)n * N;
    const float* xpb = g_xp + (size_t)b * N * L;

    for (int l = t; l < L; l += 256) xq[l] = xpb[(size_t)diag * L + l];
    __syncthreads();
    for (int m = t; m < N; m += 256) {
        const float* xm = xpb + (size_t)m * L;
        float d = 0.f;
        for (int l = 0; l < L; l++) d += xq[l] * xm[l];
        su[m] = f2key(d);
    }
    __syncthreads();

    unsigned res = 0u;
    for (int bit = 31; bit >= 0; --bit) {
        unsigned cand = res | (1u << bit);
        if (t == 0) s_cnt = 0;
        __syncthreads();
        int c = 0;
        for (int m = t; m < N; m += 256) c += (su[m] >= cand) ? 1 : 0;
#pragma unroll
        for (int o = 16; o; o >>= 1) c += __shfl_down_sync(0xffffffffu, c, o);
        if (lane == 0) atomicAdd(&s_cnt, c);
        __syncthreads();
        if (s_cnt >= K) res = cand;
        __syncthreads();
    }

    if (t == 0) s_cnt = 0;
    __syncthreads();
    {
        int c = 0;
        for (int m = t; m < N; m += 256) c += (su[m] > res) ? 1 : 0;
#pragma unroll
        for (int o = 16; o; o >>= 1) c += __shfl_down_sync(0xffffffffu, c, o);
        if (lane == 0) atomicAdd(&s_cnt, c);
    }
    __syncthreads();
    int need = K - s_cnt;
    __syncthreads();

    int running = 0;
    float vmax = -3.4e38f;
    for (int m0 = 0; m0 < N; m0 += 256) {
        int m = m0 + t;
        bool valid = (m < N);
        unsigned u = valid ? su[m] : 0u;
        bool eq = valid && (u == res);
        unsigned ball = __ballot_sync(0xffffffffu, eq);
        if (lane == 0) warp_tot[w] = __popc(ball);
        __syncthreads();
        int woff = 0, ctot = 0;
#pragma unroll
        for (int i = 0; i < 8; i++) {
            int wt = warp_tot[i];
            ctot += wt;
            if (i < w) woff += wt;
        }
        int rank = running + woff + __popc(ball & ((1u << lane) - 1u));
        if (valid) {
            bool nb2 = (u > res) || (eq && rank < need) || (m == diag);
            float s = key2f(u);
            float v = nb2 ? s : (-1e19f * s);
            sf[m] = v;
            vmax = fmaxf(vmax, v);
        }
        running += ctot;
        __syncthreads();
    }

    redf[t] = vmax; __syncthreads();
#pragma unroll
    for (int st = 128; st; st >>= 1) { if (t < st) redf[t] = fmaxf(redf[t], redf[t + st]); __syncthreads(); }
    float M = redf[0]; __syncthreads();

    float lsum = 0.f;
    for (int m = t; m < N; m += 256) {
        float e = expf(sf[m] - M);
        sf[m] = e;
        lsum += e;
    }
    __syncthreads();
    redf[t] = lsum; __syncthreads();
#pragma unroll
    for (int st = 128; st; st >>= 1) { if (t < st) redf[t] += redf[t + st]; __syncthreads(); }
    float inv = 1.0f / redf[0]; __syncthreads();

    if (t == 0) s_nnz = 0;
    __syncthreads();
    for (int m = t; m < N; m += 256) {
        float a = sf[m] * inv;
        sf[m] = a;
        row[m] = a;
        if (a != 0.f) {
            int p = atomicAdd(&s_nnz, 1);
            if (p < 1024) ilist[p] = m;
        }
    }
    __syncthreads();
    int nnz = s_nnz;

    if (t < L) {
        float acc = 0.f;
        if (nnz == 1) {
            int m = ilist[0];
            acc = sf[m] * xpb[(size_t)m * L + t];
        } else {
            for (int m = 0; m < N; m++) {
                float a = sf[m];
                if (a != 0.f) acc += a * xpb[(size_t)m * L + t];
            }
        }
        h_out[(size_t)n * L + t] = acc;
    }
}

// ---------- launch ----------
extern "C" void kernel_launch(void* const* d_in, const int* in_sizes, int n_in,
                              void* d_out, int out_size) {
    const float* x = (const float*)d_in[0];
    const float* W = (const float*)d_in[1];

    int L = (int)(sqrt((double)in_sizes[1]) + 0.5);
    long long BN = in_sizes[0] / L;
    long long N  = (long long)out_size / BN - L;
    int Ni = (int)N;
    int B  = (int)(BN / N);
    int BNi = (int)BN;

    float* h_out = (float*)d_out;
    float* attn  = h_out + (size_t)BN * L;

    proj_kernel<<<(BNi + PROJ_ROWS - 1) / PROJ_ROWS, 256>>>(x, W, BNi, L);

    int nb = (Ni + 127) / 128;
    int tri = nb * (nb + 1) / 2;
    dim3 g2(tri, B);
    score_stats_kernel<<<g2, 256>>>(Ni, L, nb);

    merge_kernel<<<(BNi + 255) / 256, 256>>>(BNi, Ni, nb, 100);

    fill_kernel<<<BNi, 256>>>(h_out, attn, Ni, L);

    size_t smem = (size_t)Ni * sizeof(float);
    attn_slow_kernel<<<BNi, 256, smem>>>(h_out, attn, Ni, L);
}